// round 12
// baseline (speedup 1.0000x reference)
#include <cuda_runtime.h>
#include <cuda_bf16.h>
#include <cstdint>

#define Bb    32
#define Ff    128
#define Hh    256
#define Nn    2048
#define Ll    2
#define Ee    262144
#define NNODE 65536   // B*N

// ---------------- scratch (device globals; no allocation allowed) ----------
__device__ float g_h1buf[(size_t)NNODE * Hh];
__device__ float g_h2buf[(size_t)NNODE * Hh];
__device__ float g_Abuf [(size_t)NNODE * Hh];
__device__ float g_Bbuf [(size_t)NNODE * Hh];
__device__ float g_agg  [(size_t)NNODE * Hh];
__device__ float g_pos  [(size_t)NNODE * 3];
__device__ float g_pos2 [(size_t)NNODE * 3];
__device__ float g_hb   [Bb * Hh];
__device__ float g_gf   [Nn * Hh];
// low-rank layer-0 products: P[r][0:256]=h@Wm1, [256:512]=h@Wm2, [512:768]=h@Wu[0:256]
// rows: 0..31 = hb, 32..2079 = gf
__device__ float g_P[(size_t)2080 * 768];
// edge sort-by-dst structures
__device__ int g_cnt [NNODE];
__device__ int g_cur [NNODE];
__device__ int g_off [NNODE + 1];
__device__ int g_bsum[256];
__device__ int g_perm[Ee];
// transposed, bf16 hi/lo split weights (layer-1 Wm at offset 2*65536; Wu both layers)
__device__ __nv_bfloat16 g_wm_h[(size_t)Ll * 2 * 256 * 256];
__device__ __nv_bfloat16 g_wm_l[(size_t)Ll * 2 * 256 * 256];
__device__ __nv_bfloat16 g_wu_h[(size_t)Ll * 256 * 512];
__device__ __nv_bfloat16 g_wu_l[(size_t)Ll * 256 * 512];

// ---------------- helpers ----------------------------------------------------
__device__ __forceinline__ uint32_t smem_u32(const void* p) {
    uint32_t a;
    asm("{ .reg .u64 t; cvta.to.shared.u64 t, %1; cvt.u32.u64 %0, t; }" : "=r"(a) : "l"(p));
    return a;
}
__device__ __forceinline__ uint32_t swz(uint32_t o) { return o ^ ((o >> 3) & 0x70); }

__device__ __forceinline__ void cpa16(uint32_t dst, const void* src) {
    asm volatile("cp.async.cg.shared.global [%0], [%1], 16;" :: "r"(dst), "l"(src));
}
#define CPCOMMIT() asm volatile("cp.async.commit_group;" ::: "memory")
#define CPWAIT0()  asm volatile("cp.async.wait_group 0;" ::: "memory")

#define LDSM4(r0, r1, r2, r3, a) \
    asm volatile("ldmatrix.sync.aligned.m8n8.x4.shared.b16 {%0,%1,%2,%3}, [%4];" \
        : "=r"(r0), "=r"(r1), "=r"(r2), "=r"(r3) : "r"(a))

#define MMA16816(d, a, b) \
    asm volatile("mma.sync.aligned.m16n8k16.row.col.f32.bf16.bf16.f32 " \
        "{%0,%1,%2,%3},{%4,%5,%6,%7},{%8,%9},{%0,%1,%2,%3};" \
        : "+f"((d)[0]), "+f"((d)[1]), "+f"((d)[2]), "+f"((d)[3]) \
        : "r"((a)[0]), "r"((a)[1]), "r"((a)[2]), "r"((a)[3]), "r"((b)[0]), "r"((b)[1]))

__device__ __forceinline__ void splitv(float v, __nv_bfloat16& h, __nv_bfloat16& l) {
    h = __float2bfloat16(v);
    l = __float2bfloat16(v - __bfloat162float(h));
}
__device__ __forceinline__ void split2(float a, float b, uint32_t& hi, uint32_t& lo) {
    __nv_bfloat16 ha, la, hb, lb;
    splitv(a, ha, la);
    splitv(b, hb, lb);
    hi = (uint32_t)__bfloat16_as_ushort(ha) | ((uint32_t)__bfloat16_as_ushort(hb) << 16);
    lo = (uint32_t)__bfloat16_as_ushort(la) | ((uint32_t)__bfloat16_as_ushort(lb) << 16);
}

// ---------------- merged weight prep ----------------------------------------
__global__ void k_wprep(const float* __restrict__ Wm, const float* __restrict__ Wu) {
    int idx = blockIdx.x * 256 + threadIdx.x;   // 393216 total
    if (idx < 131072) {
        int mat = idx >> 16;
        int r2 = idx & 65535;
        int n = r2 >> 8, k = r2 & 255;
        float v = Wm[(size_t)513 * 256 + (size_t)(mat * 256 + k) * 256 + n];
        __nv_bfloat16 h, lo;
        splitv(v, h, lo);
        size_t o = ((size_t)(2 + mat) * 256 + n) * 256 + k;
        g_wm_h[o] = h;
        g_wm_l[o] = lo;
    } else {
        int r = idx - 131072;                   // Ll*131072
        int l = r >> 17;
        int r2 = r & 131071;
        int n = r2 >> 9, k = r2 & 511;
        if (l == 0 && k < 256) return;
        float v = Wu[(size_t)l * 512 * 256 + (size_t)k * 256 + n];
        __nv_bfloat16 h, lo;
        splitv(v, h, lo);
        size_t o = (size_t)l * 131072 + (size_t)n * 512 + k;
        g_wu_h[o] = h;
        g_wu_l[o] = lo;
    }
}

// ---------------- fused meand + gfeat ----------------------------------------
__global__ void k_meandgf(const float* __restrict__ positions,
                          const float* __restrict__ Wg1, const float* __restrict__ bg1,
                          const float* __restrict__ Wg2, const float* __restrict__ bg2) {
    __shared__ float sp[Nn * 3];
    __shared__ float red[256];
    __shared__ float t[Ff];
    int i = blockIdx.x;
    for (int k = threadIdx.x; k < Nn * 3; k += 256) sp[k] = positions[k];
    __syncthreads();
    float px = sp[i * 3], py = sp[i * 3 + 1], pz = sp[i * 3 + 2];
    float sum = 0.f;
    for (int j = threadIdx.x; j < Nn; j += 256) {
        if (j == i) continue;
        float dx = px - sp[j * 3], dy = py - sp[j * 3 + 1], dz = pz - sp[j * 3 + 2];
        sum += sqrtf(dx * dx + dy * dy + dz * dz);
    }
    red[threadIdx.x] = sum;
    __syncthreads();
    for (int s = 128; s; s >>= 1) {
        if (threadIdx.x < s) red[threadIdx.x] += red[threadIdx.x + s];
        __syncthreads();
    }
    float m = red[0] / (float)(Nn - 1);
    if (threadIdx.x < 128) {
        int kk = threadIdx.x;
        float w = Wg1[kk] + Wg1[128 + kk] + Wg1[256 + kk];
        t[kk] = fmaxf(fmaf(m, w, bg1[kk]), 0.f);
    }
    __syncthreads();
    int j = threadIdx.x;
    float acc = bg2[j];
    #pragma unroll 4
    for (int kk = 0; kk < 128; kk++) acc = fmaf(t[kk], Wg2[kk * Hh + j], acc);
    g_gf[i * Hh + j] = acc;
}

// ---------------- fused hbase + initpos + cnt-zero ---------------------------
__global__ void k_hbinit(const float* __restrict__ x, const float* __restrict__ W_in,
                         const float* __restrict__ b_in, const float* __restrict__ positions) {
    if (blockIdx.x < 32) {
        __shared__ float xb[Ff];
        int b = blockIdx.x;
        if (threadIdx.x < Ff) xb[threadIdx.x] = x[b * Ff + threadIdx.x];
        __syncthreads();
        int j = threadIdx.x;
        float acc = b_in[j];
        #pragma unroll 4
        for (int k = 0; k < Ff; k++) acc = fmaf(xb[k], W_in[k * Hh + j], acc);
        g_hb[b * Hh + j] = acc;
    } else {
        int i = (blockIdx.x - 32) * 256 + threadIdx.x;
        if (i < NNODE * 3) {
            int nd = i / 3;
            int k = i - nd * 3;
            g_pos[i] = positions[(nd & 2047) * 3 + k];
        }
        if (i < NNODE) g_cnt[i] = 0;
    }
}

// ---------------- edge counting sort (by dst) -------------------------------
__global__ void k_hist(const int* __restrict__ ei) {
    int e = blockIdx.x * 256 + threadIdx.x;
    atomicAdd(&g_cnt[ei[Ee + e]], 1);
}
__global__ void k_scan1() {
    __shared__ int sh[256];
    int t = threadIdx.x, b = blockIdx.x;
    int v = g_cnt[b * 256 + t];
    sh[t] = v;
    __syncthreads();
    for (int o = 1; o < 256; o <<= 1) {
        int u = (t >= o) ? sh[t - o] : 0;
        __syncthreads();
        sh[t] += u;
        __syncthreads();
    }
    g_off[b * 256 + t] = sh[t] - v;
    if (t == 255) g_bsum[b] = sh[255];
}
__global__ void k_scan2() {
    __shared__ int sh[256];
    int t = threadIdx.x;
    int v = g_bsum[t];
    sh[t] = v;
    __syncthreads();
    for (int o = 1; o < 256; o <<= 1) {
        int u = (t >= o) ? sh[t - o] : 0;
        __syncthreads();
        sh[t] += u;
        __syncthreads();
    }
    g_bsum[t] = sh[t] - v;
}
__global__ void k_scan3() {
    int i = blockIdx.x * 256 + threadIdx.x;
    int v = g_off[i] + g_bsum[blockIdx.x];
    g_off[i] = v;
    g_cur[i] = v;
    if (i == 0) g_off[NNODE] = Ee;
}
__global__ void k_scatter(const int* __restrict__ ei) {
    int e = blockIdx.x * 256 + threadIdx.x;
    int d = ei[Ee + e];
    int p = atomicAdd(&g_cur[d], 1);
    g_perm[p] = e;
}

// ---------------- low-rank layer-0 small GEMM (software pipelined) ----------
// k unrolled x8: 24 batched weight LDGs (MLP-overlapped, L2-hit) then 384 FMAs.
__global__ __launch_bounds__(256) void k_small(const float* __restrict__ Wm,
                                               const float* __restrict__ Wu) {
    __shared__ float hs[16][257];
    int r0 = blockIdx.x * 16;
    int tid = threadIdx.x;
    for (int i = 0; i < 16; i++) {
        int r = r0 + i;
        const float* src = (r < 32) ? (g_hb + r * 256) : (g_gf + (size_t)(r - 32) * 256);
        hs[i][tid] = src[tid];
    }
    __syncthreads();
    float a1[16], a2[16], a3[16];
    #pragma unroll
    for (int i = 0; i < 16; i++) { a1[i] = 0.f; a2[i] = 0.f; a3[i] = 0.f; }

    for (int k0 = 0; k0 < 256; k0 += 8) {
        float w1r[8], w2r[8], w3r[8];
        #pragma unroll
        for (int u = 0; u < 8; u++) {
            int k = k0 + u;
            w1r[u] = __ldg(Wm + (size_t)k * 256 + tid);
            w2r[u] = __ldg(Wm + (size_t)(256 + k) * 256 + tid);
            w3r[u] = __ldg(Wu + (size_t)k * 256 + tid);
        }
        #pragma unroll
        for (int u = 0; u < 8; u++) {
            int k = k0 + u;
            #pragma unroll
            for (int i = 0; i < 16; i++) {
                float hv = hs[i][k];
                a1[i] = fmaf(hv, w1r[u], a1[i]);
                a2[i] = fmaf(hv, w2r[u], a2[i]);
                a3[i] = fmaf(hv, w3r[u], a3[i]);
            }
        }
    }
    #pragma unroll
    for (int i = 0; i < 16; i++) {
        size_t o = (size_t)(r0 + i) * 768;
        g_P[o + tid]       = a1[i];
        g_P[o + 256 + tid] = a2[i];
        g_P[o + 512 + tid] = a3[i];
    }
}

// ---------------- HMMA GEMM: single 64KB buffer, 2 CTAs/SM ------------------
#define MM_SMEM 65536

__global__ __launch_bounds__(256, 2) void k_mma(
    const float* __restrict__ A0, const float* __restrict__ A1,
    const __nv_bfloat16* __restrict__ Bh, const __nv_bfloat16* __restrict__ Bl,
    int bpitch, int cstart, int nchunks, int mode,
    const float* __restrict__ bias, const float* __restrict__ Xres,
    float* __restrict__ out0, float* __restrict__ out1,
    int zflags,
    const float* __restrict__ Wout, const float* __restrict__ bout,
    float* __restrict__ outv, int wantout)
{
    extern __shared__ char smem[];
    uint32_t sb = smem_u32(smem);
    int tid = threadIdx.x, wid = tid >> 5, lane = tid & 31;
    int row0 = blockIdx.y * 128, n0 = blockIdx.x * 128;
    int wm = wid & 3, wn = wid >> 2;

    float acc[2][8][4];
    #pragma unroll
    for (int a = 0; a < 2; a++)
        #pragma unroll
        for (int b = 0; b < 8; b++)
            #pragma unroll
            for (int c = 0; c < 4; c++) acc[a][b][c] = 0.f;

    float4 areg[8];

    auto stage_load = [&](int c) {
        const float* As = (c < 4) ? A0 : A1;
        int cb = (c & 3) * 64;
        #pragma unroll
        for (int i = 0; i < 4; i++) {
            int g = i * 256 + tid;
            int row = g >> 3, c8 = g & 7;
            const float* src = As + (size_t)(row0 + row) * 256 + cb + c8 * 8;
            areg[i * 2]     = *(const float4*)src;
            areg[i * 2 + 1] = *(const float4*)(src + 4);
        }
    };
    auto stage_store = [&]() {
        #pragma unroll
        for (int i = 0; i < 4; i++) {
            int g = i * 256 + tid;
            int row = g >> 3, c8 = g & 7;
            float4 va = areg[i * 2], vb = areg[i * 2 + 1];
            uint4 hi, lo;
            split2(va.x, va.y, hi.x, lo.x);
            split2(va.z, va.w, hi.y, lo.y);
            split2(vb.x, vb.y, hi.z, lo.z);
            split2(vb.z, vb.w, hi.w, lo.w);
            uint32_t off = swz(row * 128 + c8 * 16);
            *(uint4*)(smem + off)         = hi;
            *(uint4*)(smem + 16384 + off) = lo;
        }
    };
    auto stage_b = [&](int c) {
        uint32_t base = sb + 32768;
        #pragma unroll
        for (int i = 0; i < 8; i++) {
            int g = i * 256 + tid;
            int sp = g >> 10, r = g & 1023;
            int row = r >> 3, c8 = r & 7;
            const __nv_bfloat16* src = (sp ? Bl : Bh)
                + (size_t)(n0 + row) * bpitch + c * 64 + c8 * 8;
            cpa16(base + sp * 16384 + swz(row * 128 + c8 * 16), src);
        }
        CPCOMMIT();
    };

    stage_load(cstart);

    for (int c = cstart; c < nchunks; c++) {
        __syncthreads();
        stage_b(c);
        stage_store();
        if (c + 1 < nchunks) stage_load(c + 1);
        CPWAIT0();
        __syncthreads();

        int arow = wm * 32 + (lane & 7) + ((lane >> 3) & 1) * 8;
        int akb = ((lane >> 4) & 1) * 16;
        int brow = wn * 64 + (lane & 7) + ((lane >> 4) & 1) * 8;
        int bkb = ((lane >> 3) & 1) * 16;

        #pragma unroll
        for (int k16 = 0; k16 < 4; k16++) {
            uint32_t a_h[2][4], a_l[2][4], b_h[8][2], b_l[8][2];
            #pragma unroll
            for (int mf = 0; mf < 2; mf++) {
                uint32_t ad = sb + swz((arow + mf * 16) * 128 + k16 * 32 + akb);
                LDSM4(a_h[mf][0], a_h[mf][1], a_h[mf][2], a_h[mf][3], ad);
                LDSM4(a_l[mf][0], a_l[mf][1], a_l[mf][2], a_l[mf][3], ad + 16384);
            }
            #pragma unroll
            for (int nf2 = 0; nf2 < 4; nf2++) {
                uint32_t bd = sb + 32768 + swz((brow + nf2 * 16) * 128 + k16 * 32 + bkb);
                LDSM4(b_h[2 * nf2][0], b_h[2 * nf2][1],
                      b_h[2 * nf2 + 1][0], b_h[2 * nf2 + 1][1], bd);
                LDSM4(b_l[2 * nf2][0], b_l[2 * nf2][1],
                      b_l[2 * nf2 + 1][0], b_l[2 * nf2 + 1][1], bd + 16384);
            }
            #pragma unroll
            for (int mf = 0; mf < 2; mf++)
                #pragma unroll
                for (int nf = 0; nf < 8; nf++) {
                    MMA16816(acc[mf][nf], a_h[mf], b_h[nf]);
                    MMA16816(acc[mf][nf], a_h[mf], b_l[nf]);
                    MMA16816(acc[mf][nf], a_l[mf], b_h[nf]);
                }
        }
    }

    // ---------------- epilogue ----------------
    int r_base = row0 + wm * 32 + (lane >> 2);
    int c_base = n0 + wn * 64 + 2 * (lane & 3);
    if (mode == 0) {
        #pragma unroll
        for (int mf = 0; mf < 2; mf++)
            #pragma unroll
            for (int nf = 0; nf < 8; nf++) {
                int r = r_base + mf * 16;
                int col = c_base + nf * 8;
                float* ob = (col < 256) ? out0 : out1;
                int cc = col & 255;
                *(float2*)(ob + (size_t)r * 256 + cc) =
                    make_float2(acc[mf][nf][0], acc[mf][nf][1]);
                *(float2*)(ob + (size_t)(r + 8) * 256 + cc) =
                    make_float2(acc[mf][nf][2], acc[mf][nf][3]);
            }
        if (blockIdx.x == 0 && (zflags & 2) && tid < 128) outv[row0 + tid] = bout[0];
    } else if (mode == 1) {
        float wpart[2][2] = {{0.f, 0.f}, {0.f, 0.f}};
        #pragma unroll
        for (int mf = 0; mf < 2; mf++)
            #pragma unroll
            for (int nf = 0; nf < 8; nf++) {
                int col = c_base + nf * 8;
                float b0 = bias[col], b1 = bias[col + 1];
                float w0 = 0.f, w1 = 0.f;
                if (wantout) { w0 = Wout[col]; w1 = Wout[col + 1]; }
                #pragma unroll
                for (int hr = 0; hr < 2; hr++) {
                    int r = r_base + mf * 16 + hr * 8;
                    size_t off = (size_t)r * 256 + col;
                    float2 xv = *(const float2*)(Xres + off);
                    float o0 = xv.x + fmaxf(acc[mf][nf][hr * 2]     + b0, 0.f);
                    float o1 = xv.y + fmaxf(acc[mf][nf][hr * 2 + 1] + b1, 0.f);
                    *(float2*)(out0 + off) = make_float2(o0, o1);
                    wpart[mf][hr] += o0 * w0 + o1 * w1;
                }
            }
        if (wantout) {
            #pragma unroll
            for (int mf = 0; mf < 2; mf++)
                #pragma unroll
                for (int hr = 0; hr < 2; hr++) {
                    float v = wpart[mf][hr];
                    v += __shfl_xor_sync(0xffffffffu, v, 1);
                    v += __shfl_xor_sync(0xffffffffu, v, 2);
                    if ((lane & 3) == 0)
                        atomicAdd(outv + r_base + mf * 16 + hr * 8, v);
                }
        }
    } else {
        #pragma unroll
        for (int mf = 0; mf < 2; mf++)
            #pragma unroll
            for (int nf = 0; nf < 8; nf++) {
                int col = c_base + nf * 8;
                float b0 = bias[col], b1 = bias[col + 1];
                #pragma unroll
                for (int hr = 0; hr < 2; hr++) {
                    int r = r_base + mf * 16 + hr * 8;
                    int bb = r >> 11, nn = r & 2047;
                    const float* hbr = g_hb + bb * 256 + col;
                    const float* gfr = g_gf + (size_t)nn * 256 + col;
                    const float* phr = g_P + (size_t)bb * 768 + 512 + col;
                    const float* pgr = g_P + (size_t)(32 + nn) * 768 + 512 + col;
                    float x0 = hbr[0] + gfr[0];
                    float x1 = hbr[1] + gfr[1];
                    float ci0 = phr[0] + pgr[0];
                    float ci1 = phr[1] + pgr[1];
                    float o0 = x0 + fmaxf(acc[mf][nf][hr * 2]     + ci0 + b0, 0.f);
                    float o1 = x1 + fmaxf(acc[mf][nf][hr * 2 + 1] + ci1 + b1, 0.f);
                    *(float2*)(out0 + (size_t)r * 256 + col) = make_float2(o0, o1);
                }
            }
    }
}

// ---------------- edge kernels: 1 warp / dst node ---------------------------
__global__ __launch_bounds__(256) void k_edge2_lr(const int* __restrict__ ei,
                                                  const float* __restrict__ wd,
                                                  const float* __restrict__ bmv,
                                                  const float* __restrict__ wp) {
    int node = (blockIdx.x << 3) + (threadIdx.x >> 5);
    int lane = threadIdx.x & 31;
    int beg = g_off[node], end = g_off[node + 1];
    int j0 = lane << 3;

    float4 w0 = *(const float4*)(wd + j0),  w1 = *(const float4*)(wd + j0 + 4);
    float4 c0 = *(const float4*)(bmv + j0), c1 = *(const float4*)(bmv + j0 + 4);
    float4 p0 = *(const float4*)(wp + j0),  p1 = *(const float4*)(wp + j0 + 4);

    int bt = node >> 11, nt = node & 2047;
    const float4* pb = (const float4*)(g_P + (size_t)bt * 768 + 256 + j0);
    const float4* pg = (const float4*)(g_P + (size_t)(32 + nt) * 768 + 256 + j0);
    float4 q0 = pb[0], q1 = pb[1], r0 = pg[0], r1 = pg[1];
    float4 b0 = make_float4(q0.x + r0.x, q0.y + r0.y, q0.z + r0.z, q0.w + r0.w);
    float4 b1 = make_float4(q1.x + r1.x, q1.y + r1.y, q1.z + r1.z, q1.w + r1.w);

    float ptx = g_pos[node * 3], pty = g_pos[node * 3 + 1], ptz = g_pos[node * 3 + 2];

    float4 ag0 = make_float4(0.f, 0.f, 0.f, 0.f);
    float4 ag1 = make_float4(0.f, 0.f, 0.f, 0.f);
    float pa = 0.f;

    for (int i = beg; i < end; i++) {
        int e = g_perm[i];
        int s = __ldg(ei + e);
        float psx = g_pos[s * 3], psy = g_pos[s * 3 + 1], psz = g_pos[s * 3 + 2];
        float dx = psx - ptx, dy = psy - pty, dz = psz - ptz;
        float d = sqrtf(dx * dx + dy * dy + dz * dz + 1e-12f);

        int bs = s >> 11, ns = s & 2047;
        const float4* ab = (const float4*)(g_P + (size_t)bs * 768 + j0);
        const float4* ag4 = (const float4*)(g_P + (size_t)(32 + ns) * 768 + j0);
        float4 u0 = ab[0], u1 = ab[1], v0 = ag4[0], v1 = ag4[1];
        float4 a0 = make_float4(u0.x + v0.x, u0.y + v0.y, u0.z + v0.z, u0.w + v0.w);
        float4 a1 = make_float4(u1.x + v1.x, u1.y + v1.y, u1.z + v1.z, u1.w + v1.w);

        float4 m0, m1;
        m0.x = fmaxf(fmaf(d, w0.x, a0.x + b0.x + c0.x), 0.f);
        m0.y = fmaxf(fmaf(d, w0.y, a0.y + b0.y + c0.y), 0.f);
        m0.z = fmaxf(fmaf(d, w0.z, a0.z + b0.z + c0.z), 0.f);
        m0.w = fmaxf(fmaf(d, w0.w, a0.w + b0.w + c0.w), 0.f);
        m1.x = fmaxf(fmaf(d, w1.x, a1.x + b1.x + c1.x), 0.f);
        m1.y = fmaxf(fmaf(d, w1.y, a1.y + b1.y + c1.y), 0.f);
        m1.z = fmaxf(fmaf(d, w1.z, a1.z + b1.z + c1.z), 0.f);
        m1.w = fmaxf(fmaf(d, w1.w, a1.w + b1.w + c1.w), 0.f);

        ag0.x += m0.x; ag0.y += m0.y; ag0.z += m0.z; ag0.w += m0.w;
        ag1.x += m1.x; ag1.y += m1.y; ag1.z += m1.z; ag1.w += m1.w;

        float cf = m0.x * p0.x + m0.y * p0.y + m0.z * p0.z + m0.w * p0.w
                 + m1.x * p1.x + m1.y * p1.y + m1.z * p1.z + m1.w * p1.w;
        #pragma unroll
        for (int off = 16; off; off >>= 1) cf += __shfl_xor_sync(0xffffffffu, cf, off);

        if (lane < 3) {
            float pd = (lane == 0) ? (ptx - psx) : (lane == 1) ? (pty - psy) : (ptz - psz);
            pa += pd * cf;
        }
    }

    float* ag = g_agg + ((size_t)node << 8) + j0;
    *(float4*)ag       = ag0;
    *(float4*)(ag + 4) = ag1;
    if (lane < 3) {
        float pt = (lane == 0) ? ptx : (lane == 1) ? pty : ptz;
        g_pos2[node * 3 + lane] = pt + pa * 0.25f;
    }
}

__global__ __launch_bounds__(256) void k_edge_l1(const int* __restrict__ ei,
                                                 const float* __restrict__ wd,
                                                 const float* __restrict__ bmv) {
    int node = (blockIdx.x << 3) + (threadIdx.x >> 5);
    int lane = threadIdx.x & 31;
    int beg = g_off[node], end = g_off[node + 1];
    int j0 = lane << 3;

    float4 w0 = *(const float4*)(wd + j0),  w1 = *(const float4*)(wd + j0 + 4);
    float4 c0 = *(const float4*)(bmv + j0), c1 = *(const float4*)(bmv + j0 + 4);
    const float4* B4 = (const float4*)(g_Bbuf + ((size_t)node << 8) + j0);
    float4 b0 = B4[0], b1 = B4[1];
    float ptx = g_pos2[node * 3], pty = g_pos2[node * 3 + 1], ptz = g_pos2[node * 3 + 2];

    float4 ag0 = make_float4(0.f, 0.f, 0.f, 0.f);
    float4 ag1 = make_float4(0.f, 0.f, 0.f, 0.f);

    for (int i = beg; i < end; i++) {
        int e = g_perm[i];
        int s = __ldg(ei + e);
        float psx = g_pos2[s * 3], psy = g_pos2[s * 3 + 1], psz = g_pos2[s * 3 + 2];
        float dx = psx - ptx, dy = psy - pty, dz = psz - ptz;
        float d = sqrtf(dx * dx + dy * dy + dz * dz + 1e-12f);

        const float4* A4 = (const float4*)(g_Abuf + ((size_t)s << 8) + j0);
        float4 a0 = A4[0], a1 = A4[1];

        ag0.x += fmaxf(fmaf(d, w0.x, a0.x + b0.x + c0.x), 0.f);
        ag0.y += fmaxf(fmaf(d, w0.y, a0.y + b0.y + c0.y), 0.f);
        ag0.z += fmaxf(fmaf(d, w0.z, a0.z + b0.z + c0.z), 0.f);
        ag0.w += fmaxf(fmaf(d, w0.w, a0.w + b0.w + c0.w), 0.f);
        ag1.x += fmaxf(fmaf(d, w1.x, a1.x + b1.x + c1.x), 0.f);
        ag1.y += fmaxf(fmaf(d, w1.y, a1.y + b1.y + c1.y), 0.f);
        ag1.z += fmaxf(fmaf(d, w1.z, a1.z + b1.z + c1.z), 0.f);
        ag1.w += fmaxf(fmaf(d, w1.w, a1.w + b1.w + c1.w), 0.f);
    }

    float* ag = g_agg + ((size_t)node << 8) + j0;
    *(float4*)ag       = ag0;
    *(float4*)(ag + 4) = ag1;
}

// ---------------- launch ----------------------------------------------------
extern "C" void kernel_launch(void* const* d_in, const int* in_sizes, int n_in,
                              void* d_out, int out_size) {
    const float* x         = (const float*)d_in[0];
    const float* positions = (const float*)d_in[1];
    const float* W_in      = (const float*)d_in[2];
    const float* b_in      = (const float*)d_in[3];
    const float* Wg1       = (const float*)d_in[4];
    const float* bg1       = (const float*)d_in[5];
    const float* Wg2       = (const float*)d_in[6];
    const float* bg2       = (const float*)d_in[7];
    const float* Wm        = (const float*)d_in[8];
    const float* bm        = (const float*)d_in[9];
    const float* Wu        = (const float*)d_in[10];
    const float* bu        = (const float*)d_in[11];
    const float* Wp        = (const float*)d_in[12];
    const float* Wout      = (const float*)d_in[13];
    const float* bout      = (const float*)d_in[14];
    const int*   ei        = (const int*)d_in[15];
    float* out = (float*)d_out;

    static float* h1 = nullptr;
    static float* h2 = nullptr;
    static float* abuf = nullptr;
    static float* bbuf = nullptr;
    static float* aggp = nullptr;
    static __nv_bfloat16 *wmh, *wml, *wuh, *wul;
    if (!h1) {
        cudaGetSymbolAddress((void**)&h1,   g_h1buf);
        cudaGetSymbolAddress((void**)&h2,   g_h2buf);
        cudaGetSymbolAddress((void**)&abuf, g_Abuf);
        cudaGetSymbolAddress((void**)&bbuf, g_Bbuf);
        cudaGetSymbolAddress((void**)&aggp, g_agg);
        cudaGetSymbolAddress((void**)&wmh,  g_wm_h);
        cudaGetSymbolAddress((void**)&wml,  g_wm_l);
        cudaGetSymbolAddress((void**)&wuh,  g_wu_h);
        cudaGetSymbolAddress((void**)&wul,  g_wu_l);
        cudaFuncSetAttribute(k_mma, cudaFuncAttributeMaxDynamicSharedMemorySize, MM_SMEM);
    }

    // prologue (fused)
    k_wprep<<<1536, 256>>>(Wm, Wu);
    k_meandgf<<<Nn, 256>>>(positions, Wg1, bg1, Wg2, bg2);
    k_hbinit<<<800, 256>>>(x, W_in, b_in, positions);
    k_small<<<130, 256>>>(Wm, Wu);
    k_hist<<<Ee / 256, 256>>>(ei);
    k_scan1<<<256, 256>>>();
    k_scan2<<<1, 256>>>();
    k_scan3<<<256, 256>>>();
    k_scatter<<<Ee / 256, 256>>>(ei);

    // ---- layer 0 (low-rank h0 path; pos2 = pos + delta fused in edge) ----
    k_edge2_lr<<<NNODE / 8, 256>>>(ei, Wm + 512 * 256, bm, Wp);
    k_mma<<<dim3(2, NNODE / 128), 256, MM_SMEM>>>(
        nullptr, aggp, wuh, wul, 512, 4, 8, 2,
        bu, nullptr, h1, nullptr, 0, nullptr, nullptr, nullptr, 0);

    // ---- layer 1 (full-rank; pos dead after, edge slimmed) ----
    const float* Wml = Wm + (size_t)513 * 256;
    k_mma<<<dim3(4, NNODE / 128), 256, MM_SMEM>>>(
        h1, nullptr, wmh + (size_t)2 * 65536, wml + (size_t)2 * 65536,
        256, 0, 4, 0, nullptr, nullptr, abuf, bbuf,
        2, nullptr, bout, out, 0);
    k_edge_l1<<<NNODE / 8, 256>>>(ei, Wml + 512 * 256, bm + 256);
    k_mma<<<dim3(2, NNODE / 128), 256, MM_SMEM>>>(
        h1, aggp, wuh + 131072, wul + 131072, 512, 0, 8, 1,
        bu + 256, h1, h2, nullptr, 0, Wout, bout, out, 1);
}

// round 13
// speedup vs baseline: 1.4793x; 1.4793x over previous
#include <cuda_runtime.h>
#include <cuda_bf16.h>
#include <cstdint>

#define Bb    32
#define Ff    128
#define Hh    256
#define Nn    2048
#define Ll    2
#define Ee    262144
#define NNODE 65536   // B*N

// ---------------- scratch (device globals; no allocation allowed) ----------
__device__ float g_h1buf[(size_t)NNODE * Hh];
__device__ float g_h2buf[(size_t)NNODE * Hh];
__device__ float g_Abuf [(size_t)NNODE * Hh];
__device__ float g_Bbuf [(size_t)NNODE * Hh];
__device__ float g_agg  [(size_t)NNODE * Hh];
__device__ float g_pos  [(size_t)NNODE * 3];
__device__ float g_pos2 [(size_t)NNODE * 3];
__device__ float g_hb   [Bb * Hh];
__device__ float g_gf   [Nn * Hh];
// low-rank layer-0 products: P[r][0:256]=h@Wm1, [256:512]=h@Wm2, [512:768]=h@Wu[0:256]
// rows: 0..31 = hb, 32..2079 = gf
__device__ float g_P[(size_t)2080 * 768];
// edge sort-by-dst structures
__device__ int g_cnt [NNODE];
__device__ int g_cur [NNODE];
__device__ int g_off [NNODE + 1];
__device__ int g_bsum[256];
__device__ int g_perm[Ee];
// transposed, bf16 hi/lo split weights (layer-1 Wm at offset 2*65536; Wu both layers)
__device__ __nv_bfloat16 g_wm_h[(size_t)Ll * 2 * 256 * 256];
__device__ __nv_bfloat16 g_wm_l[(size_t)Ll * 2 * 256 * 256];
__device__ __nv_bfloat16 g_wu_h[(size_t)Ll * 256 * 512];
__device__ __nv_bfloat16 g_wu_l[(size_t)Ll * 256 * 512];

// ---------------- helpers ----------------------------------------------------
__device__ __forceinline__ uint32_t smem_u32(const void* p) {
    uint32_t a;
    asm("{ .reg .u64 t; cvta.to.shared.u64 t, %1; cvt.u32.u64 %0, t; }" : "=r"(a) : "l"(p));
    return a;
}
__device__ __forceinline__ uint32_t swz(uint32_t o) { return o ^ ((o >> 3) & 0x70); }

__device__ __forceinline__ void cpa16(uint32_t dst, const void* src) {
    asm volatile("cp.async.cg.shared.global [%0], [%1], 16;" :: "r"(dst), "l"(src));
}
#define CPCOMMIT() asm volatile("cp.async.commit_group;" ::: "memory")
#define CPWAIT0()  asm volatile("cp.async.wait_group 0;" ::: "memory")

#define LDSM4(r0, r1, r2, r3, a) \
    asm volatile("ldmatrix.sync.aligned.m8n8.x4.shared.b16 {%0,%1,%2,%3}, [%4];" \
        : "=r"(r0), "=r"(r1), "=r"(r2), "=r"(r3) : "r"(a))

#define MMA16816(d, a, b) \
    asm volatile("mma.sync.aligned.m16n8k16.row.col.f32.bf16.bf16.f32 " \
        "{%0,%1,%2,%3},{%4,%5,%6,%7},{%8,%9},{%0,%1,%2,%3};" \
        : "+f"((d)[0]), "+f"((d)[1]), "+f"((d)[2]), "+f"((d)[3]) \
        : "r"((a)[0]), "r"((a)[1]), "r"((a)[2]), "r"((a)[3]), "r"((b)[0]), "r"((b)[1]))

__device__ __forceinline__ void splitv(float v, __nv_bfloat16& h, __nv_bfloat16& l) {
    h = __float2bfloat16(v);
    l = __float2bfloat16(v - __bfloat162float(h));
}
__device__ __forceinline__ void split2(float a, float b, uint32_t& hi, uint32_t& lo) {
    __nv_bfloat16 ha, la, hb, lb;
    splitv(a, ha, la);
    splitv(b, hb, lb);
    hi = (uint32_t)__bfloat16_as_ushort(ha) | ((uint32_t)__bfloat16_as_ushort(hb) << 16);
    lo = (uint32_t)__bfloat16_as_ushort(la) | ((uint32_t)__bfloat16_as_ushort(lb) << 16);
}

// ---------------- merged weight prep ----------------------------------------
__global__ void k_wprep(const float* __restrict__ Wm, const float* __restrict__ Wu) {
    int idx = blockIdx.x * 256 + threadIdx.x;   // 393216 total
    if (idx < 131072) {
        int mat = idx >> 16;
        int r2 = idx & 65535;
        int n = r2 >> 8, k = r2 & 255;
        float v = Wm[(size_t)513 * 256 + (size_t)(mat * 256 + k) * 256 + n];
        __nv_bfloat16 h, lo;
        splitv(v, h, lo);
        size_t o = ((size_t)(2 + mat) * 256 + n) * 256 + k;
        g_wm_h[o] = h;
        g_wm_l[o] = lo;
    } else {
        int r = idx - 131072;                   // Ll*131072
        int l = r >> 17;
        int r2 = r & 131071;
        int n = r2 >> 9, k = r2 & 511;
        if (l == 0 && k < 256) return;
        float v = Wu[(size_t)l * 512 * 256 + (size_t)k * 256 + n];
        __nv_bfloat16 h, lo;
        splitv(v, h, lo);
        size_t o = (size_t)l * 131072 + (size_t)n * 512 + k;
        g_wu_h[o] = h;
        g_wu_l[o] = lo;
    }
}

// ---------------- fused meand + gfeat ----------------------------------------
__global__ void k_meandgf(const float* __restrict__ positions,
                          const float* __restrict__ Wg1, const float* __restrict__ bg1,
                          const float* __restrict__ Wg2, const float* __restrict__ bg2) {
    __shared__ float sp[Nn * 3];
    __shared__ float red[256];
    __shared__ float t[Ff];
    int i = blockIdx.x;
    for (int k = threadIdx.x; k < Nn * 3; k += 256) sp[k] = positions[k];
    __syncthreads();
    float px = sp[i * 3], py = sp[i * 3 + 1], pz = sp[i * 3 + 2];
    float sum = 0.f;
    for (int j = threadIdx.x; j < Nn; j += 256) {
        if (j == i) continue;
        float dx = px - sp[j * 3], dy = py - sp[j * 3 + 1], dz = pz - sp[j * 3 + 2];
        sum += sqrtf(dx * dx + dy * dy + dz * dz);
    }
    red[threadIdx.x] = sum;
    __syncthreads();
    for (int s = 128; s; s >>= 1) {
        if (threadIdx.x < s) red[threadIdx.x] += red[threadIdx.x + s];
        __syncthreads();
    }
    float m = red[0] / (float)(Nn - 1);
    if (threadIdx.x < 128) {
        int kk = threadIdx.x;
        float w = Wg1[kk] + Wg1[128 + kk] + Wg1[256 + kk];
        t[kk] = fmaxf(fmaf(m, w, bg1[kk]), 0.f);
    }
    __syncthreads();
    int j = threadIdx.x;
    float acc = bg2[j];
    #pragma unroll 4
    for (int kk = 0; kk < 128; kk++) acc = fmaf(t[kk], Wg2[kk * Hh + j], acc);
    g_gf[i * Hh + j] = acc;
}

// ---------------- fused hbase + initpos + cnt-zero ---------------------------
__global__ void k_hbinit(const float* __restrict__ x, const float* __restrict__ W_in,
                         const float* __restrict__ b_in, const float* __restrict__ positions) {
    if (blockIdx.x < 32) {
        __shared__ float xb[Ff];
        int b = blockIdx.x;
        if (threadIdx.x < Ff) xb[threadIdx.x] = x[b * Ff + threadIdx.x];
        __syncthreads();
        int j = threadIdx.x;
        float acc = b_in[j];
        #pragma unroll 4
        for (int k = 0; k < Ff; k++) acc = fmaf(xb[k], W_in[k * Hh + j], acc);
        g_hb[b * Hh + j] = acc;
    } else {
        int i = (blockIdx.x - 32) * 256 + threadIdx.x;
        if (i < NNODE * 3) {
            int nd = i / 3;
            int k = i - nd * 3;
            g_pos[i] = positions[(nd & 2047) * 3 + k];
        }
        if (i < NNODE) g_cnt[i] = 0;
    }
}

// ---------------- edge counting sort (by dst) -------------------------------
__global__ void k_hist(const int* __restrict__ ei) {
    int e = blockIdx.x * 256 + threadIdx.x;
    atomicAdd(&g_cnt[ei[Ee + e]], 1);
}
__global__ void k_scan1() {
    __shared__ int sh[256];
    int t = threadIdx.x, b = blockIdx.x;
    int v = g_cnt[b * 256 + t];
    sh[t] = v;
    __syncthreads();
    for (int o = 1; o < 256; o <<= 1) {
        int u = (t >= o) ? sh[t - o] : 0;
        __syncthreads();
        sh[t] += u;
        __syncthreads();
    }
    g_off[b * 256 + t] = sh[t] - v;
    if (t == 255) g_bsum[b] = sh[255];
}
__global__ void k_scan2() {
    __shared__ int sh[256];
    int t = threadIdx.x;
    int v = g_bsum[t];
    sh[t] = v;
    __syncthreads();
    for (int o = 1; o < 256; o <<= 1) {
        int u = (t >= o) ? sh[t - o] : 0;
        __syncthreads();
        sh[t] += u;
        __syncthreads();
    }
    g_bsum[t] = sh[t] - v;
}
__global__ void k_scan3() {
    int i = blockIdx.x * 256 + threadIdx.x;
    int v = g_off[i] + g_bsum[blockIdx.x];
    g_off[i] = v;
    g_cur[i] = v;
    if (i == 0) g_off[NNODE] = Ee;
}
__global__ void k_scatter(const int* __restrict__ ei) {
    int e = blockIdx.x * 256 + threadIdx.x;
    int d = ei[Ee + e];
    int p = atomicAdd(&g_cur[d], 1);
    g_perm[p] = e;
}

// ---------------- low-rank layer-0 small GEMM (split by matrix) -------------
// grid 390: grp = bx/3 selects 16 rows, mat = bx%3 selects weight matrix.
// Per CTA: 16 acc regs/thread, k unrolled x8 with batched weight LDGs.
__global__ __launch_bounds__(256) void k_small(const float* __restrict__ Wm,
                                               const float* __restrict__ Wu) {
    __shared__ float hs[16][257];
    int grp = blockIdx.x / 3;
    int mat = blockIdx.x - grp * 3;
    int r0 = grp * 16;
    int tid = threadIdx.x;
    for (int i = 0; i < 16; i++) {
        int r = r0 + i;
        const float* src = (r < 32) ? (g_hb + r * 256) : (g_gf + (size_t)(r - 32) * 256);
        hs[i][tid] = src[tid];
    }
    __syncthreads();

    const float* W = (mat == 0) ? Wm : (mat == 1) ? (Wm + 256 * 256) : Wu;
    float a[16];
    #pragma unroll
    for (int i = 0; i < 16; i++) a[i] = 0.f;

    for (int k0 = 0; k0 < 256; k0 += 8) {
        float wr[8];
        #pragma unroll
        for (int u = 0; u < 8; u++)
            wr[u] = __ldg(W + (size_t)(k0 + u) * 256 + tid);
        #pragma unroll
        for (int u = 0; u < 8; u++) {
            int k = k0 + u;
            #pragma unroll
            for (int i = 0; i < 16; i++)
                a[i] = fmaf(hs[i][k], wr[u], a[i]);
        }
    }
    #pragma unroll
    for (int i = 0; i < 16; i++)
        g_P[(size_t)(r0 + i) * 768 + mat * 256 + tid] = a[i];
}

// ---------------- HMMA GEMM: single 64KB buffer, 2 CTAs/SM ------------------
#define MM_SMEM 65536

__global__ __launch_bounds__(256, 2) void k_mma(
    const float* __restrict__ A0, const float* __restrict__ A1,
    const __nv_bfloat16* __restrict__ Bh, const __nv_bfloat16* __restrict__ Bl,
    int bpitch, int cstart, int nchunks, int mode,
    const float* __restrict__ bias, const float* __restrict__ Xres,
    float* __restrict__ out0, float* __restrict__ out1,
    int zflags,
    const float* __restrict__ Wout, const float* __restrict__ bout,
    float* __restrict__ outv, int wantout)
{
    extern __shared__ char smem[];
    uint32_t sb = smem_u32(smem);
    int tid = threadIdx.x, wid = tid >> 5, lane = tid & 31;
    int row0 = blockIdx.y * 128, n0 = blockIdx.x * 128;
    int wm = wid & 3, wn = wid >> 2;

    float acc[2][8][4];
    #pragma unroll
    for (int a = 0; a < 2; a++)
        #pragma unroll
        for (int b = 0; b < 8; b++)
            #pragma unroll
            for (int c = 0; c < 4; c++) acc[a][b][c] = 0.f;

    float4 areg[8];

    auto stage_load = [&](int c) {
        const float* As = (c < 4) ? A0 : A1;
        int cb = (c & 3) * 64;
        #pragma unroll
        for (int i = 0; i < 4; i++) {
            int g = i * 256 + tid;
            int row = g >> 3, c8 = g & 7;
            const float* src = As + (size_t)(row0 + row) * 256 + cb + c8 * 8;
            areg[i * 2]     = *(const float4*)src;
            areg[i * 2 + 1] = *(const float4*)(src + 4);
        }
    };
    auto stage_store = [&]() {
        #pragma unroll
        for (int i = 0; i < 4; i++) {
            int g = i * 256 + tid;
            int row = g >> 3, c8 = g & 7;
            float4 va = areg[i * 2], vb = areg[i * 2 + 1];
            uint4 hi, lo;
            split2(va.x, va.y, hi.x, lo.x);
            split2(va.z, va.w, hi.y, lo.y);
            split2(vb.x, vb.y, hi.z, lo.z);
            split2(vb.z, vb.w, hi.w, lo.w);
            uint32_t off = swz(row * 128 + c8 * 16);
            *(uint4*)(smem + off)         = hi;
            *(uint4*)(smem + 16384 + off) = lo;
        }
    };
    auto stage_b = [&](int c) {
        uint32_t base = sb + 32768;
        #pragma unroll
        for (int i = 0; i < 8; i++) {
            int g = i * 256 + tid;
            int sp = g >> 10, r = g & 1023;
            int row = r >> 3, c8 = r & 7;
            const __nv_bfloat16* src = (sp ? Bl : Bh)
                + (size_t)(n0 + row) * bpitch + c * 64 + c8 * 8;
            cpa16(base + sp * 16384 + swz(row * 128 + c8 * 16), src);
        }
        CPCOMMIT();
    };

    stage_load(cstart);

    for (int c = cstart; c < nchunks; c++) {
        __syncthreads();
        stage_b(c);
        stage_store();
        if (c + 1 < nchunks) stage_load(c + 1);
        CPWAIT0();
        __syncthreads();

        int arow = wm * 32 + (lane & 7) + ((lane >> 3) & 1) * 8;
        int akb = ((lane >> 4) & 1) * 16;
        int brow = wn * 64 + (lane & 7) + ((lane >> 4) & 1) * 8;
        int bkb = ((lane >> 3) & 1) * 16;

        #pragma unroll
        for (int k16 = 0; k16 < 4; k16++) {
            uint32_t a_h[2][4], a_l[2][4], b_h[8][2], b_l[8][2];
            #pragma unroll
            for (int mf = 0; mf < 2; mf++) {
                uint32_t ad = sb + swz((arow + mf * 16) * 128 + k16 * 32 + akb);
                LDSM4(a_h[mf][0], a_h[mf][1], a_h[mf][2], a_h[mf][3], ad);
                LDSM4(a_l[mf][0], a_l[mf][1], a_l[mf][2], a_l[mf][3], ad + 16384);
            }
            #pragma unroll
            for (int nf2 = 0; nf2 < 4; nf2++) {
                uint32_t bd = sb + 32768 + swz((brow + nf2 * 16) * 128 + k16 * 32 + bkb);
                LDSM4(b_h[2 * nf2][0], b_h[2 * nf2][1],
                      b_h[2 * nf2 + 1][0], b_h[2 * nf2 + 1][1], bd);
                LDSM4(b_l[2 * nf2][0], b_l[2 * nf2][1],
                      b_l[2 * nf2 + 1][0], b_l[2 * nf2 + 1][1], bd + 16384);
            }
            #pragma unroll
            for (int mf = 0; mf < 2; mf++)
                #pragma unroll
                for (int nf = 0; nf < 8; nf++) {
                    MMA16816(acc[mf][nf], a_h[mf], b_h[nf]);
                    MMA16816(acc[mf][nf], a_h[mf], b_l[nf]);
                    MMA16816(acc[mf][nf], a_l[mf], b_h[nf]);
                }
        }
    }

    // ---------------- epilogue ----------------
    int r_base = row0 + wm * 32 + (lane >> 2);
    int c_base = n0 + wn * 64 + 2 * (lane & 3);
    if (mode == 0) {
        #pragma unroll
        for (int mf = 0; mf < 2; mf++)
            #pragma unroll
            for (int nf = 0; nf < 8; nf++) {
                int r = r_base + mf * 16;
                int col = c_base + nf * 8;
                float* ob = (col < 256) ? out0 : out1;
                int cc = col & 255;
                *(float2*)(ob + (size_t)r * 256 + cc) =
                    make_float2(acc[mf][nf][0], acc[mf][nf][1]);
                *(float2*)(ob + (size_t)(r + 8) * 256 + cc) =
                    make_float2(acc[mf][nf][2], acc[mf][nf][3]);
            }
        if (blockIdx.x == 0 && (zflags & 2) && tid < 128) outv[row0 + tid] = bout[0];
    } else if (mode == 1) {
        float wpart[2][2] = {{0.f, 0.f}, {0.f, 0.f}};
        #pragma unroll
        for (int mf = 0; mf < 2; mf++)
            #pragma unroll
            for (int nf = 0; nf < 8; nf++) {
                int col = c_base + nf * 8;
                float b0 = bias[col], b1 = bias[col + 1];
                float w0 = 0.f, w1 = 0.f;
                if (wantout) { w0 = Wout[col]; w1 = Wout[col + 1]; }
                #pragma unroll
                for (int hr = 0; hr < 2; hr++) {
                    int r = r_base + mf * 16 + hr * 8;
                    size_t off = (size_t)r * 256 + col;
                    float2 xv = *(const float2*)(Xres + off);
                    float o0 = xv.x + fmaxf(acc[mf][nf][hr * 2]     + b0, 0.f);
                    float o1 = xv.y + fmaxf(acc[mf][nf][hr * 2 + 1] + b1, 0.f);
                    *(float2*)(out0 + off) = make_float2(o0, o1);
                    wpart[mf][hr] += o0 * w0 + o1 * w1;
                }
            }
        if (wantout) {
            #pragma unroll
            for (int mf = 0; mf < 2; mf++)
                #pragma unroll
                for (int hr = 0; hr < 2; hr++) {
                    float v = wpart[mf][hr];
                    v += __shfl_xor_sync(0xffffffffu, v, 1);
                    v += __shfl_xor_sync(0xffffffffu, v, 2);
                    if ((lane & 3) == 0)
                        atomicAdd(outv + r_base + mf * 16 + hr * 8, v);
                }
        }
    } else {
        #pragma unroll
        for (int mf = 0; mf < 2; mf++)
            #pragma unroll
            for (int nf = 0; nf < 8; nf++) {
                int col = c_base + nf * 8;
                float b0 = bias[col], b1 = bias[col + 1];
                #pragma unroll
                for (int hr = 0; hr < 2; hr++) {
                    int r = r_base + mf * 16 + hr * 8;
                    int bb = r >> 11, nn = r & 2047;
                    const float* hbr = g_hb + bb * 256 + col;
                    const float* gfr = g_gf + (size_t)nn * 256 + col;
                    const float* phr = g_P + (size_t)bb * 768 + 512 + col;
                    const float* pgr = g_P + (size_t)(32 + nn) * 768 + 512 + col;
                    float x0 = hbr[0] + gfr[0];
                    float x1 = hbr[1] + gfr[1];
                    float ci0 = phr[0] + pgr[0];
                    float ci1 = phr[1] + pgr[1];
                    float o0 = x0 + fmaxf(acc[mf][nf][hr * 2]     + ci0 + b0, 0.f);
                    float o1 = x1 + fmaxf(acc[mf][nf][hr * 2 + 1] + ci1 + b1, 0.f);
                    *(float2*)(out0 + (size_t)r * 256 + col) = make_float2(o0, o1);
                }
            }
    }
}

// ---------------- edge kernels: 1 warp / dst node ---------------------------
__global__ __launch_bounds__(256) void k_edge2_lr(const int* __restrict__ ei,
                                                  const float* __restrict__ wd,
                                                  const float* __restrict__ bmv,
                                                  const float* __restrict__ wp) {
    int node = (blockIdx.x << 3) + (threadIdx.x >> 5);
    int lane = threadIdx.x & 31;
    int beg = g_off[node], end = g_off[node + 1];
    int j0 = lane << 3;

    float4 w0 = *(const float4*)(wd + j0),  w1 = *(const float4*)(wd + j0 + 4);
    float4 c0 = *(const float4*)(bmv + j0), c1 = *(const float4*)(bmv + j0 + 4);
    float4 p0 = *(const float4*)(wp + j0),  p1 = *(const float4*)(wp + j0 + 4);

    int bt = node >> 11, nt = node & 2047;
    const float4* pb = (const float4*)(g_P + (size_t)bt * 768 + 256 + j0);
    const float4* pg = (const float4*)(g_P + (size_t)(32 + nt) * 768 + 256 + j0);
    float4 q0 = pb[0], q1 = pb[1], r0 = pg[0], r1 = pg[1];
    float4 b0 = make_float4(q0.x + r0.x, q0.y + r0.y, q0.z + r0.z, q0.w + r0.w);
    float4 b1 = make_float4(q1.x + r1.x, q1.y + r1.y, q1.z + r1.z, q1.w + r1.w);

    float ptx = g_pos[node * 3], pty = g_pos[node * 3 + 1], ptz = g_pos[node * 3 + 2];

    float4 ag0 = make_float4(0.f, 0.f, 0.f, 0.f);
    float4 ag1 = make_float4(0.f, 0.f, 0.f, 0.f);
    float pa = 0.f;

    for (int i = beg; i < end; i++) {
        int e = g_perm[i];
        int s = __ldg(ei + e);
        float psx = g_pos[s * 3], psy = g_pos[s * 3 + 1], psz = g_pos[s * 3 + 2];
        float dx = psx - ptx, dy = psy - pty, dz = psz - ptz;
        float d = sqrtf(dx * dx + dy * dy + dz * dz + 1e-12f);

        int bs = s >> 11, ns = s & 2047;
        const float4* ab = (const float4*)(g_P + (size_t)bs * 768 + j0);
        const float4* ag4 = (const float4*)(g_P + (size_t)(32 + ns) * 768 + j0);
        float4 u0 = ab[0], u1 = ab[1], v0 = ag4[0], v1 = ag4[1];
        float4 a0 = make_float4(u0.x + v0.x, u0.y + v0.y, u0.z + v0.z, u0.w + v0.w);
        float4 a1 = make_float4(u1.x + v1.x, u1.y + v1.y, u1.z + v1.z, u1.w + v1.w);

        float4 m0, m1;
        m0.x = fmaxf(fmaf(d, w0.x, a0.x + b0.x + c0.x), 0.f);
        m0.y = fmaxf(fmaf(d, w0.y, a0.y + b0.y + c0.y), 0.f);
        m0.z = fmaxf(fmaf(d, w0.z, a0.z + b0.z + c0.z), 0.f);
        m0.w = fmaxf(fmaf(d, w0.w, a0.w + b0.w + c0.w), 0.f);
        m1.x = fmaxf(fmaf(d, w1.x, a1.x + b1.x + c1.x), 0.f);
        m1.y = fmaxf(fmaf(d, w1.y, a1.y + b1.y + c1.y), 0.f);
        m1.z = fmaxf(fmaf(d, w1.z, a1.z + b1.z + c1.z), 0.f);
        m1.w = fmaxf(fmaf(d, w1.w, a1.w + b1.w + c1.w), 0.f);

        ag0.x += m0.x; ag0.y += m0.y; ag0.z += m0.z; ag0.w += m0.w;
        ag1.x += m1.x; ag1.y += m1.y; ag1.z += m1.z; ag1.w += m1.w;

        float cf = m0.x * p0.x + m0.y * p0.y + m0.z * p0.z + m0.w * p0.w
                 + m1.x * p1.x + m1.y * p1.y + m1.z * p1.z + m1.w * p1.w;
        #pragma unroll
        for (int off = 16; off; off >>= 1) cf += __shfl_xor_sync(0xffffffffu, cf, off);

        if (lane < 3) {
            float pd = (lane == 0) ? (ptx - psx) : (lane == 1) ? (pty - psy) : (ptz - psz);
            pa += pd * cf;
        }
    }

    float* ag = g_agg + ((size_t)node << 8) + j0;
    *(float4*)ag       = ag0;
    *(float4*)(ag + 4) = ag1;
    if (lane < 3) {
        float pt = (lane == 0) ? ptx : (lane == 1) ? pty : ptz;
        g_pos2[node * 3 + lane] = pt + pa * 0.25f;
    }
}

__global__ __launch_bounds__(256) void k_edge_l1(const int* __restrict__ ei,
                                                 const float* __restrict__ wd,
                                                 const float* __restrict__ bmv) {
    int node = (blockIdx.x << 3) + (threadIdx.x >> 5);
    int lane = threadIdx.x & 31;
    int beg = g_off[node], end = g_off[node + 1];
    int j0 = lane << 3;

    float4 w0 = *(const float4*)(wd + j0),  w1 = *(const float4*)(wd + j0 + 4);
    float4 c0 = *(const float4*)(bmv + j0), c1 = *(const float4*)(bmv + j0 + 4);
    const float4* B4 = (const float4*)(g_Bbuf + ((size_t)node << 8) + j0);
    float4 b0 = B4[0], b1 = B4[1];
    float ptx = g_pos2[node * 3], pty = g_pos2[node * 3 + 1], ptz = g_pos2[node * 3 + 2];

    float4 ag0 = make_float4(0.f, 0.f, 0.f, 0.f);
    float4 ag1 = make_float4(0.f, 0.f, 0.f, 0.f);

    for (int i = beg; i < end; i++) {
        int e = g_perm[i];
        int s = __ldg(ei + e);
        float psx = g_pos2[s * 3], psy = g_pos2[s * 3 + 1], psz = g_pos2[s * 3 + 2];
        float dx = psx - ptx, dy = psy - pty, dz = psz - ptz;
        float d = sqrtf(dx * dx + dy * dy + dz * dz + 1e-12f);

        const float4* A4 = (const float4*)(g_Abuf + ((size_t)s << 8) + j0);
        float4 a0 = A4[0], a1 = A4[1];

        ag0.x += fmaxf(fmaf(d, w0.x, a0.x + b0.x + c0.x), 0.f);
        ag0.y += fmaxf(fmaf(d, w0.y, a0.y + b0.y + c0.y), 0.f);
        ag0.z += fmaxf(fmaf(d, w0.z, a0.z + b0.z + c0.z), 0.f);
        ag0.w += fmaxf(fmaf(d, w0.w, a0.w + b0.w + c0.w), 0.f);
        ag1.x += fmaxf(fmaf(d, w1.x, a1.x + b1.x + c1.x), 0.f);
        ag1.y += fmaxf(fmaf(d, w1.y, a1.y + b1.y + c1.y), 0.f);
        ag1.z += fmaxf(fmaf(d, w1.z, a1.z + b1.z + c1.z), 0.f);
        ag1.w += fmaxf(fmaf(d, w1.w, a1.w + b1.w + c1.w), 0.f);
    }

    float* ag = g_agg + ((size_t)node << 8) + j0;
    *(float4*)ag       = ag0;
    *(float4*)(ag + 4) = ag1;
}

// ---------------- launch ----------------------------------------------------
extern "C" void kernel_launch(void* const* d_in, const int* in_sizes, int n_in,
                              void* d_out, int out_size) {
    const float* x         = (const float*)d_in[0];
    const float* positions = (const float*)d_in[1];
    const float* W_in      = (const float*)d_in[2];
    const float* b_in      = (const float*)d_in[3];
    const float* Wg1       = (const float*)d_in[4];
    const float* bg1       = (const float*)d_in[5];
    const float* Wg2       = (const float*)d_in[6];
    const float* bg2       = (const float*)d_in[7];
    const float* Wm        = (const float*)d_in[8];
    const float* bm        = (const float*)d_in[9];
    const float* Wu        = (const float*)d_in[10];
    const float* bu        = (const float*)d_in[11];
    const float* Wp        = (const float*)d_in[12];
    const float* Wout      = (const float*)d_in[13];
    const float* bout      = (const float*)d_in[14];
    const int*   ei        = (const int*)d_in[15];
    float* out = (float*)d_out;

    static float* h1 = nullptr;
    static float* h2 = nullptr;
    static float* abuf = nullptr;
    static float* bbuf = nullptr;
    static float* aggp = nullptr;
    static __nv_bfloat16 *wmh, *wml, *wuh, *wul;
    if (!h1) {
        cudaGetSymbolAddress((void**)&h1,   g_h1buf);
        cudaGetSymbolAddress((void**)&h2,   g_h2buf);
        cudaGetSymbolAddress((void**)&abuf, g_Abuf);
        cudaGetSymbolAddress((void**)&bbuf, g_Bbuf);
        cudaGetSymbolAddress((void**)&aggp, g_agg);
        cudaGetSymbolAddress((void**)&wmh,  g_wm_h);
        cudaGetSymbolAddress((void**)&wml,  g_wm_l);
        cudaGetSymbolAddress((void**)&wuh,  g_wu_h);
        cudaGetSymbolAddress((void**)&wul,  g_wu_l);
        cudaFuncSetAttribute(k_mma, cudaFuncAttributeMaxDynamicSharedMemorySize, MM_SMEM);
    }

    // prologue (fused)
    k_wprep<<<1536, 256>>>(Wm, Wu);
    k_meandgf<<<Nn, 256>>>(positions, Wg1, bg1, Wg2, bg2);
    k_hbinit<<<800, 256>>>(x, W_in, b_in, positions);
    k_small<<<390, 256>>>(Wm, Wu);
    k_hist<<<Ee / 256, 256>>>(ei);
    k_scan1<<<256, 256>>>();
    k_scan2<<<1, 256>>>();
    k_scan3<<<256, 256>>>();
    k_scatter<<<Ee / 256, 256>>>(ei);

    // ---- layer 0 (low-rank h0 path; pos2 = pos + delta fused in edge) ----
    k_edge2_lr<<<NNODE / 8, 256>>>(ei, Wm + 512 * 256, bm, Wp);
    k_mma<<<dim3(2, NNODE / 128), 256, MM_SMEM>>>(
        nullptr, aggp, wuh, wul, 512, 4, 8, 2,
        bu, nullptr, h1, nullptr, 0, nullptr, nullptr, nullptr, 0);

    // ---- layer 1 (full-rank; pos dead after, edge slimmed) ----
    const float* Wml = Wm + (size_t)513 * 256;
    k_mma<<<dim3(4, NNODE / 128), 256, MM_SMEM>>>(
        h1, nullptr, wmh + (size_t)2 * 65536, wml + (size_t)2 * 65536,
        256, 0, 4, 0, nullptr, nullptr, abuf, bbuf,
        2, nullptr, bout, out, 0);
    k_edge_l1<<<NNODE / 8, 256>>>(ei, Wml + 512 * 256, bm + 256);
    k_mma<<<dim3(2, NNODE / 128), 256, MM_SMEM>>>(
        h1, aggp, wuh + 131072, wul + 131072, 512, 0, 8, 1,
        bu + 256, h1, h2, nullptr, 0, Wout, bout, out, 1);
}

// round 15
// speedup vs baseline: 1.5210x; 1.0282x over previous
#include <cuda_runtime.h>
#include <cuda_bf16.h>
#include <cstdint>

#define Bb    32
#define Ff    128
#define Hh    256
#define Nn    2048
#define Ll    2
#define Ee    262144
#define NNODE 65536   // B*N

// ---------------- scratch (device globals; no allocation allowed) ----------
__device__ float g_h1buf[(size_t)NNODE * Hh];
__device__ float g_h2buf[(size_t)NNODE * Hh];
__device__ float g_Abuf [(size_t)NNODE * Hh];
__device__ float g_Bbuf [(size_t)NNODE * Hh];
__device__ float g_agg  [(size_t)NNODE * Hh];
__device__ float g_pos  [(size_t)NNODE * 3];
__device__ float g_pos2 [(size_t)NNODE * 3];
__device__ float g_hb   [Bb * Hh];
__device__ float g_gf   [Nn * Hh];
// low-rank layer-0 products: P[r][0:256]=h@Wm1, [256:512]=h@Wm2, [512:768]=h@Wu[0:256]
__device__ float g_P[(size_t)2080 * 768];
// edge sort-by-dst structures
__device__ int g_cnt [NNODE];
__device__ int g_cur [NNODE];
__device__ int g_off [NNODE + 1];
__device__ int g_bsum[256];
__device__ int g_perm[Ee];
// transposed, bf16 hi/lo split weights (layer-1 Wm at offset 2*65536; Wu both layers)
__device__ __nv_bfloat16 g_wm_h[(size_t)Ll * 2 * 256 * 256];
__device__ __nv_bfloat16 g_wm_l[(size_t)Ll * 2 * 256 * 256];
__device__ __nv_bfloat16 g_wu_h[(size_t)Ll * 256 * 512];
__device__ __nv_bfloat16 g_wu_l[(size_t)Ll * 256 * 512];

// ---------------- helpers ----------------------------------------------------
__device__ __forceinline__ uint32_t smem_u32(const void* p) {
    uint32_t a;
    asm("{ .reg .u64 t; cvta.to.shared.u64 t, %1; cvt.u32.u64 %0, t; }" : "=r"(a) : "l"(p));
    return a;
}
__device__ __forceinline__ uint32_t swz(uint32_t o) { return o ^ ((o >> 3) & 0x70); }

__device__ __forceinline__ void cpa16(uint32_t dst, const void* src) {
    asm volatile("cp.async.cg.shared.global [%0], [%1], 16;" :: "r"(dst), "l"(src));
}
#define CPCOMMIT() asm volatile("cp.async.commit_group;" ::: "memory")
#define CPWAIT0()  asm volatile("cp.async.wait_group 0;" ::: "memory")

#define LDSM4(r0, r1, r2, r3, a) \
    asm volatile("ldmatrix.sync.aligned.m8n8.x4.shared.b16 {%0,%1,%2,%3}, [%4];" \
        : "=r"(r0), "=r"(r1), "=r"(r2), "=r"(r3) : "r"(a))

#define MMA16816(d, a, b) \
    asm volatile("mma.sync.aligned.m16n8k16.row.col.f32.bf16.bf16.f32 " \
        "{%0,%1,%2,%3},{%4,%5,%6,%7},{%8,%9},{%0,%1,%2,%3};" \
        : "+f"((d)[0]), "+f"((d)[1]), "+f"((d)[2]), "+f"((d)[3]) \
        : "r"((a)[0]), "r"((a)[1]), "r"((a)[2]), "r"((a)[3]), "r"((b)[0]), "r"((b)[1]))

__device__ __forceinline__ void splitv(float v, __nv_bfloat16& h, __nv_bfloat16& l) {
    h = __float2bfloat16(v);
    l = __float2bfloat16(v - __bfloat162float(h));
}
__device__ __forceinline__ void split2(float a, float b, uint32_t& hi, uint32_t& lo) {
    __nv_bfloat16 ha, la, hb, lb;
    splitv(a, ha, la);
    splitv(b, hb, lb);
    hi = (uint32_t)__bfloat16_as_ushort(ha) | ((uint32_t)__bfloat16_as_ushort(hb) << 16);
    lo = (uint32_t)__bfloat16_as_ushort(la) | ((uint32_t)__bfloat16_as_ushort(lb) << 16);
}

// ---------------- weight prep: coalesced 32x32 tile transpose ---------------
// 320 tiles: [0,128) layer-1 Wm (2 mats x 64 tiles); [128,192) Wu l0 agg-half;
// [192,320) Wu l1 (16 k-tiles x 8 n-tiles). Block 256 = 32x8.
__global__ __launch_bounds__(256) void k_wprep(const float* __restrict__ Wm,
                                               const float* __restrict__ Wu) {
    __shared__ float tile[32][33];
    int t = blockIdx.x;
    const float* src;
    __nv_bfloat16 *dh, *dl;
    int kbase, nbase, pitch;
    if (t < 128) {
        int mat = t >> 6, r = t & 63;
        int kt = r >> 3, nt = r & 7;
        src = Wm + (size_t)513 * 256 + (size_t)mat * 256 * 256;
        dh = g_wm_h + (size_t)(2 + mat) * 65536;
        dl = g_wm_l + (size_t)(2 + mat) * 65536;
        kbase = kt * 32; nbase = nt * 32; pitch = 256;
    } else if (t < 192) {
        int r = t - 128;
        int kt = r >> 3, nt = r & 7;
        src = Wu;
        dh = g_wu_h; dl = g_wu_l;
        kbase = 256 + kt * 32; nbase = nt * 32; pitch = 512;
    } else {
        int r = t - 192;
        int kt = r >> 3, nt = r & 7;
        src = Wu + (size_t)512 * 256;
        dh = g_wu_h + 131072; dl = g_wu_l + 131072;
        kbase = kt * 32; nbase = nt * 32; pitch = 512;
    }
    int tx = threadIdx.x & 31, ty = threadIdx.x >> 5;
    #pragma unroll
    for (int i = 0; i < 4; i++) {
        int k = kbase + ty + i * 8;
        tile[ty + i * 8][tx] = src[(size_t)k * 256 + nbase + tx];
    }
    __syncthreads();
    #pragma unroll
    for (int i = 0; i < 4; i++) {
        int n = nbase + ty + i * 8;
        float v = tile[tx][ty + i * 8];   // = src[kbase+tx][n]
        __nv_bfloat16 h, lo;
        splitv(v, h, lo);
        size_t o = (size_t)n * pitch + kbase + tx;
        dh[o] = h;
        dl[o] = lo;
    }
}

// ---------------- fused meand + gfeat ----------------------------------------
__global__ void k_meandgf(const float* __restrict__ positions,
                          const float* __restrict__ Wg1, const float* __restrict__ bg1,
                          const float* __restrict__ Wg2, const float* __restrict__ bg2) {
    __shared__ float sp[Nn * 3];
    __shared__ float red[256];
    __shared__ float t[Ff];
    int i = blockIdx.x;
    for (int k = threadIdx.x; k < Nn * 3; k += 256) sp[k] = positions[k];
    __syncthreads();
    float px = sp[i * 3], py = sp[i * 3 + 1], pz = sp[i * 3 + 2];
    float sum = 0.f;
    for (int j = threadIdx.x; j < Nn; j += 256) {
        if (j == i) continue;
        float dx = px - sp[j * 3], dy = py - sp[j * 3 + 1], dz = pz - sp[j * 3 + 2];
        sum += sqrtf(dx * dx + dy * dy + dz * dz);
    }
    red[threadIdx.x] = sum;
    __syncthreads();
    for (int s = 128; s; s >>= 1) {
        if (threadIdx.x < s) red[threadIdx.x] += red[threadIdx.x + s];
        __syncthreads();
    }
    float m = red[0] / (float)(Nn - 1);
    if (threadIdx.x < 128) {
        int kk = threadIdx.x;
        float w = Wg1[kk] + Wg1[128 + kk] + Wg1[256 + kk];
        t[kk] = fmaxf(fmaf(m, w, bg1[kk]), 0.f);
    }
    __syncthreads();
    int j = threadIdx.x;
    float acc = bg2[j];
    #pragma unroll 4
    for (int kk = 0; kk < 128; kk++) acc = fmaf(t[kk], Wg2[kk * Hh + j], acc);
    g_gf[i * Hh + j] = acc;
}

// ---------------- fused hbase + initpos + cnt-zero ---------------------------
__global__ void k_hbinit(const float* __restrict__ x, const float* __restrict__ W_in,
                         const float* __restrict__ b_in, const float* __restrict__ positions) {
    if (blockIdx.x < 32) {
        __shared__ float xb[Ff];
        int b = blockIdx.x;
        if (threadIdx.x < Ff) xb[threadIdx.x] = x[b * Ff + threadIdx.x];
        __syncthreads();
        int j = threadIdx.x;
        float acc = b_in[j];
        #pragma unroll 4
        for (int k = 0; k < Ff; k++) acc = fmaf(xb[k], W_in[k * Hh + j], acc);
        g_hb[b * Hh + j] = acc;
    } else {
        int i = (blockIdx.x - 32) * 256 + threadIdx.x;
        if (i < NNODE * 3) {
            int nd = i / 3;
            int k = i - nd * 3;
            g_pos[i] = positions[(nd & 2047) * 3 + k];
        }
        if (i < NNODE) g_cnt[i] = 0;
    }
}

// ---------------- edge counting sort (by dst) -------------------------------
__global__ void k_hist(const int* __restrict__ ei) {
    int e = blockIdx.x * 256 + threadIdx.x;
    atomicAdd(&g_cnt[ei[Ee + e]], 1);
}
__global__ void k_scan1() {
    __shared__ int sh[256];
    int t = threadIdx.x, b = blockIdx.x;
    int v = g_cnt[b * 256 + t];
    sh[t] = v;
    __syncthreads();
    for (int o = 1; o < 256; o <<= 1) {
        int u = (t >= o) ? sh[t - o] : 0;
        __syncthreads();
        sh[t] += u;
        __syncthreads();
    }
    g_off[b * 256 + t] = sh[t] - v;
    if (t == 255) g_bsum[b] = sh[255];
}
__global__ void k_scan2() {
    __shared__ int sh[256];
    int t = threadIdx.x;
    int v = g_bsum[t];
    sh[t] = v;
    __syncthreads();
    for (int o = 1; o < 256; o <<= 1) {
        int u = (t >= o) ? sh[t - o] : 0;
        __syncthreads();
        sh[t] += u;
        __syncthreads();
    }
    g_bsum[t] = sh[t] - v;
}
__global__ void k_scan3() {
    int i = blockIdx.x * 256 + threadIdx.x;
    int v = g_off[i] + g_bsum[blockIdx.x];
    g_off[i] = v;
    g_cur[i] = v;
    if (i == 0) g_off[NNODE] = Ee;
}
__global__ void k_scatter(const int* __restrict__ ei) {
    int e = blockIdx.x * 256 + threadIdx.x;
    int d = ei[Ee + e];
    int p = atomicAdd(&g_cur[d], 1);
    g_perm[p] = e;
}

// ---------------- low-rank layer-0 small GEMM (split by matrix, vec LDS) ----
// grid 390: grp = bx/3 rows, mat = bx%3 weight matrix. hs rows padded to 260
// (16B-aligned) so h is read via LDS.128 — 4x fewer shared loads.
__global__ __launch_bounds__(256) void k_small(const float* __restrict__ Wm,
                                               const float* __restrict__ Wu) {
    __shared__ float hs[16][260];
    int grp = blockIdx.x / 3;
    int mat = blockIdx.x - grp * 3;
    int r0 = grp * 16;
    int tid = threadIdx.x;
    for (int i = 0; i < 16; i++) {
        int r = r0 + i;
        const float* src = (r < 32) ? (g_hb + r * 256) : (g_gf + (size_t)(r - 32) * 256);
        hs[i][tid] = src[tid];
    }
    __syncthreads();

    const float* W = (mat == 0) ? Wm : (mat == 1) ? (Wm + 256 * 256) : Wu;
    float a[16];
    #pragma unroll
    for (int i = 0; i < 16; i++) a[i] = 0.f;

    for (int k0 = 0; k0 < 256; k0 += 8) {
        float wr[8];
        #pragma unroll
        for (int u = 0; u < 8; u++)
            wr[u] = __ldg(W + (size_t)(k0 + u) * 256 + tid);
        #pragma unroll
        for (int i = 0; i < 16; i++) {
            float4 h0 = *(const float4*)&hs[i][k0];
            float4 h1 = *(const float4*)&hs[i][k0 + 4];
            float ai = a[i];
            ai = fmaf(h0.x, wr[0], ai);
            ai = fmaf(h0.y, wr[1], ai);
            ai = fmaf(h0.z, wr[2], ai);
            ai = fmaf(h0.w, wr[3], ai);
            ai = fmaf(h1.x, wr[4], ai);
            ai = fmaf(h1.y, wr[5], ai);
            ai = fmaf(h1.z, wr[6], ai);
            ai = fmaf(h1.w, wr[7], ai);
            a[i] = ai;
        }
    }
    #pragma unroll
    for (int i = 0; i < 16; i++)
        g_P[(size_t)(r0 + i) * 768 + mat * 256 + tid] = a[i];
}

// ---------------- HMMA GEMM: single 64KB buffer, 2 CTAs/SM ------------------
#define MM_SMEM 65536

__global__ __launch_bounds__(256, 2) void k_mma(
    const float* __restrict__ A0, const float* __restrict__ A1,
    const __nv_bfloat16* __restrict__ Bh, const __nv_bfloat16* __restrict__ Bl,
    int bpitch, int cstart, int nchunks, int mode,
    const float* __restrict__ bias, const float* __restrict__ Xres,
    float* __restrict__ out0, float* __restrict__ out1,
    int zflags,
    const float* __restrict__ Wout, const float* __restrict__ bout,
    float* __restrict__ outv, int wantout)
{
    extern __shared__ char smem[];
    uint32_t sb = smem_u32(smem);
    int tid = threadIdx.x, wid = tid >> 5, lane = tid & 31;
    int row0 = blockIdx.y * 128, n0 = blockIdx.x * 128;
    int wm = wid & 3, wn = wid >> 2;

    float acc[2][8][4];
    #pragma unroll
    for (int a = 0; a < 2; a++)
        #pragma unroll
        for (int b = 0; b < 8; b++)
            #pragma unroll
            for (int c = 0; c < 4; c++) acc[a][b][c] = 0.f;

    float4 areg[8];

    auto stage_load = [&](int c) {
        const float* As = (c < 4) ? A0 : A1;
        int cb = (c & 3) * 64;
        #pragma unroll
        for (int i = 0; i < 4; i++) {
            int g = i * 256 + tid;
            int row = g >> 3, c8 = g & 7;
            const float* src = As + (size_t)(row0 + row) * 256 + cb + c8 * 8;
            areg[i * 2]     = *(const float4*)src;
            areg[i * 2 + 1] = *(const float4*)(src + 4);
        }
    };
    auto stage_store = [&]() {
        #pragma unroll
        for (int i = 0; i < 4; i++) {
            int g = i * 256 + tid;
            int row = g >> 3, c8 = g & 7;
            float4 va = areg[i * 2], vb = areg[i * 2 + 1];
            uint4 hi, lo;
            split2(va.x, va.y, hi.x, lo.x);
            split2(va.z, va.w, hi.y, lo.y);
            split2(vb.x, vb.y, hi.z, lo.z);
            split2(vb.z, vb.w, hi.w, lo.w);
            uint32_t off = swz(row * 128 + c8 * 16);
            *(uint4*)(smem + off)         = hi;
            *(uint4*)(smem + 16384 + off) = lo;
        }
    };
    auto stage_b = [&](int c) {
        uint32_t base = sb + 32768;
        #pragma unroll
        for (int i = 0; i < 8; i++) {
            int g = i * 256 + tid;
            int sp = g >> 10, r = g & 1023;
            int row = r >> 3, c8 = r & 7;
            const __nv_bfloat16* src = (sp ? Bl : Bh)
                + (size_t)(n0 + row) * bpitch + c * 64 + c8 * 8;
            cpa16(base + sp * 16384 + swz(row * 128 + c8 * 16), src);
        }
        CPCOMMIT();
    };

    stage_load(cstart);

    for (int c = cstart; c < nchunks; c++) {
        __syncthreads();
        stage_b(c);
        stage_store();
        if (c + 1 < nchunks) stage_load(c + 1);
        CPWAIT0();
        __syncthreads();

        int arow = wm * 32 + (lane & 7) + ((lane >> 3) & 1) * 8;
        int akb = ((lane >> 4) & 1) * 16;
        int brow = wn * 64 + (lane & 7) + ((lane >> 4) & 1) * 8;
        int bkb = ((lane >> 3) & 1) * 16;

        #pragma unroll
        for (int k16 = 0; k16 < 4; k16++) {
            uint32_t a_h[2][4], a_l[2][4], b_h[8][2], b_l[8][2];
            #pragma unroll
            for (int mf = 0; mf < 2; mf++) {
                uint32_t ad = sb + swz((arow + mf * 16) * 128 + k16 * 32 + akb);
                LDSM4(a_h[mf][0], a_h[mf][1], a_h[mf][2], a_h[mf][3], ad);
                LDSM4(a_l[mf][0], a_l[mf][1], a_l[mf][2], a_l[mf][3], ad + 16384);
            }
            #pragma unroll
            for (int nf2 = 0; nf2 < 4; nf2++) {
                uint32_t bd = sb + 32768 + swz((brow + nf2 * 16) * 128 + k16 * 32 + bkb);
                LDSM4(b_h[2 * nf2][0], b_h[2 * nf2][1],
                      b_h[2 * nf2 + 1][0], b_h[2 * nf2 + 1][1], bd);
                LDSM4(b_l[2 * nf2][0], b_l[2 * nf2][1],
                      b_l[2 * nf2 + 1][0], b_l[2 * nf2 + 1][1], bd + 16384);
            }
            #pragma unroll
            for (int mf = 0; mf < 2; mf++)
                #pragma unroll
                for (int nf = 0; nf < 8; nf++) {
                    MMA16816(acc[mf][nf], a_h[mf], b_h[nf]);
                    MMA16816(acc[mf][nf], a_h[mf], b_l[nf]);
                    MMA16816(acc[mf][nf], a_l[mf], b_h[nf]);
                }
        }
    }

    // ---------------- epilogue ----------------
    int r_base = row0 + wm * 32 + (lane >> 2);
    int c_base = n0 + wn * 64 + 2 * (lane & 3);
    if (mode == 0) {
        #pragma unroll
        for (int mf = 0; mf < 2; mf++)
            #pragma unroll
            for (int nf = 0; nf < 8; nf++) {
                int r = r_base + mf * 16;
                int col = c_base + nf * 8;
                float* ob = (col < 256) ? out0 : out1;
                int cc = col & 255;
                *(float2*)(ob + (size_t)r * 256 + cc) =
                    make_float2(acc[mf][nf][0], acc[mf][nf][1]);
                *(float2*)(ob + (size_t)(r + 8) * 256 + cc) =
                    make_float2(acc[mf][nf][2], acc[mf][nf][3]);
            }
        if (blockIdx.x == 0 && (zflags & 2) && tid < 128) outv[row0 + tid] = bout[0];
    } else if (mode == 1) {
        float wpart[2][2] = {{0.f, 0.f}, {0.f, 0.f}};
        #pragma unroll
        for (int mf = 0; mf < 2; mf++)
            #pragma unroll
            for (int nf = 0; nf < 8; nf++) {
                int col = c_base + nf * 8;
                float b0 = bias[col], b1 = bias[col + 1];
                float w0 = 0.f, w1 = 0.f;
                if (wantout) { w0 = Wout[col]; w1 = Wout[col + 1]; }
                #pragma unroll
                for (int hr = 0; hr < 2; hr++) {
                    int r = r_base + mf * 16 + hr * 8;
                    size_t off = (size_t)r * 256 + col;
                    float2 xv = *(const float2*)(Xres + off);
                    float o0 = xv.x + fmaxf(acc[mf][nf][hr * 2]     + b0, 0.f);
                    float o1 = xv.y + fmaxf(acc[mf][nf][hr * 2 + 1] + b1, 0.f);
                    *(float2*)(out0 + off) = make_float2(o0, o1);
                    wpart[mf][hr] += o0 * w0 + o1 * w1;
                }
            }
        if (wantout) {
            #pragma unroll
            for (int mf = 0; mf < 2; mf++)
                #pragma unroll
                for (int hr = 0; hr < 2; hr++) {
                    float v = wpart[mf][hr];
                    v += __shfl_xor_sync(0xffffffffu, v, 1);
                    v += __shfl_xor_sync(0xffffffffu, v, 2);
                    if ((lane & 3) == 0)
                        atomicAdd(outv + r_base + mf * 16 + hr * 8, v);
                }
        }
    } else {
        #pragma unroll
        for (int mf = 0; mf < 2; mf++)
            #pragma unroll
            for (int nf = 0; nf < 8; nf++) {
                int col = c_base + nf * 8;
                float b0 = bias[col], b1 = bias[col + 1];
                #pragma unroll
                for (int hr = 0; hr < 2; hr++) {
                    int r = r_base + mf * 16 + hr * 8;
                    int bb = r >> 11, nn = r & 2047;
                    const float* hbr = g_hb + bb * 256 + col;
                    const float* gfr = g_gf + (size_t)nn * 256 + col;
                    const float* phr = g_P + (size_t)bb * 768 + 512 + col;
                    const float* pgr = g_P + (size_t)(32 + nn) * 768 + 512 + col;
                    float x0 = hbr[0] + gfr[0];
                    float x1 = hbr[1] + gfr[1];
                    float ci0 = phr[0] + pgr[0];
                    float ci1 = phr[1] + pgr[1];
                    float o0 = x0 + fmaxf(acc[mf][nf][hr * 2]     + ci0 + b0, 0.f);
                    float o1 = x1 + fmaxf(acc[mf][nf][hr * 2 + 1] + ci1 + b1, 0.f);
                    *(float2*)(out0 + (size_t)r * 256 + col) = make_float2(o0, o1);
                }
            }
    }
}

// ---------------- edge kernels: 1 warp / dst node ---------------------------
__global__ __launch_bounds__(256) void k_edge2_lr(const int* __restrict__ ei,
                                                  const float* __restrict__ wd,
                                                  const float* __restrict__ bmv,
                                                  const float* __restrict__ wp) {
    int node = (blockIdx.x << 3) + (threadIdx.x >> 5);
    int lane = threadIdx.x & 31;
    int beg = g_off[node], end = g_off[node + 1];
    int j0 = lane << 3;

    float4 w0 = *(const float4*)(wd + j0),  w1 = *(const float4*)(wd + j0 + 4);
    float4 c0 = *(const float4*)(bmv + j0), c1 = *(const float4*)(bmv + j0 + 4);
    float4 p0 = *(const float4*)(wp + j0),  p1 = *(const float4*)(wp + j0 + 4);

    int bt = node >> 11, nt = node & 2047;
    const float4* pb = (const float4*)(g_P + (size_t)bt * 768 + 256 + j0);
    const float4* pg = (const float4*)(g_P + (size_t)(32 + nt) * 768 + 256 + j0);
    float4 q0 = pb[0], q1 = pb[1], r0 = pg[0], r1 = pg[1];
    float4 b0 = make_float4(q0.x + r0.x, q0.y + r0.y, q0.z + r0.z, q0.w + r0.w);
    float4 b1 = make_float4(q1.x + r1.x, q1.y + r1.y, q1.z + r1.z, q1.w + r1.w);

    float ptx = g_pos[node * 3], pty = g_pos[node * 3 + 1], ptz = g_pos[node * 3 + 2];

    float4 ag0 = make_float4(0.f, 0.f, 0.f, 0.f);
    float4 ag1 = make_float4(0.f, 0.f, 0.f, 0.f);
    float pa = 0.f;

    for (int i = beg; i < end; i++) {
        int e = g_perm[i];
        int s = __ldg(ei + e);
        float psx = g_pos[s * 3], psy = g_pos[s * 3 + 1], psz = g_pos[s * 3 + 2];
        float dx = psx - ptx, dy = psy - pty, dz = psz - ptz;
        float d = sqrtf(dx * dx + dy * dy + dz * dz + 1e-12f);

        int bs = s >> 11, ns = s & 2047;
        const float4* ab = (const float4*)(g_P + (size_t)bs * 768 + j0);
        const float4* ag4 = (const float4*)(g_P + (size_t)(32 + ns) * 768 + j0);
        float4 u0 = ab[0], u1 = ab[1], v0 = ag4[0], v1 = ag4[1];
        float4 a0 = make_float4(u0.x + v0.x, u0.y + v0.y, u0.z + v0.z, u0.w + v0.w);
        float4 a1 = make_float4(u1.x + v1.x, u1.y + v1.y, u1.z + v1.z, u1.w + v1.w);

        float4 m0, m1;
        m0.x = fmaxf(fmaf(d, w0.x, a0.x + b0.x + c0.x), 0.f);
        m0.y = fmaxf(fmaf(d, w0.y, a0.y + b0.y + c0.y), 0.f);
        m0.z = fmaxf(fmaf(d, w0.z, a0.z + b0.z + c0.z), 0.f);
        m0.w = fmaxf(fmaf(d, w0.w, a0.w + b0.w + c0.w), 0.f);
        m1.x = fmaxf(fmaf(d, w1.x, a1.x + b1.x + c1.x), 0.f);
        m1.y = fmaxf(fmaf(d, w1.y, a1.y + b1.y + c1.y), 0.f);
        m1.z = fmaxf(fmaf(d, w1.z, a1.z + b1.z + c1.z), 0.f);
        m1.w = fmaxf(fmaf(d, w1.w, a1.w + b1.w + c1.w), 0.f);

        ag0.x += m0.x; ag0.y += m0.y; ag0.z += m0.z; ag0.w += m0.w;
        ag1.x += m1.x; ag1.y += m1.y; ag1.z += m1.z; ag1.w += m1.w;

        float cf = m0.x * p0.x + m0.y * p0.y + m0.z * p0.z + m0.w * p0.w
                 + m1.x * p1.x + m1.y * p1.y + m1.z * p1.z + m1.w * p1.w;
        #pragma unroll
        for (int off = 16; off; off >>= 1) cf += __shfl_xor_sync(0xffffffffu, cf, off);

        if (lane < 3) {
            float pd = (lane == 0) ? (ptx - psx) : (lane == 1) ? (pty - psy) : (ptz - psz);
            pa += pd * cf;
        }
    }

    float* ag = g_agg + ((size_t)node << 8) + j0;
    *(float4*)ag       = ag0;
    *(float4*)(ag + 4) = ag1;
    if (lane < 3) {
        float pt = (lane == 0) ? ptx : (lane == 1) ? pty : ptz;
        g_pos2[node * 3 + lane] = pt + pa * 0.25f;
    }
}

__global__ __launch_bounds__(256) void k_edge_l1(const int* __restrict__ ei,
                                                 const float* __restrict__ wd,
                                                 const float* __restrict__ bmv) {
    int node = (blockIdx.x << 3) + (threadIdx.x >> 5);
    int lane = threadIdx.x & 31;
    int beg = g_off[node], end = g_off[node + 1];
    int j0 = lane << 3;

    float4 w0 = *(const float4*)(wd + j0),  w1 = *(const float4*)(wd + j0 + 4);
    float4 c0 = *(const float4*)(bmv + j0), c1 = *(const float4*)(bmv + j0 + 4);
    const float4* B4 = (const float4*)(g_Bbuf + ((size_t)node << 8) + j0);
    float4 b0 = B4[0], b1 = B4[1];
    float ptx = g_pos2[node * 3], pty = g_pos2[node * 3 + 1], ptz = g_pos2[node * 3 + 2];

    float4 ag0 = make_float4(0.f, 0.f, 0.f, 0.f);
    float4 ag1 = make_float4(0.f, 0.f, 0.f, 0.f);

    for (int i = beg; i < end; i++) {
        int e = g_perm[i];
        int s = __ldg(ei + e);
        float psx = g_pos2[s * 3], psy = g_pos2[s * 3 + 1], psz = g_pos2[s * 3 + 2];
        float dx = psx - ptx, dy = psy - pty, dz = psz - ptz;
        float d = sqrtf(dx * dx + dy * dy + dz * dz + 1e-12f);

        const float4* A4 = (const float4*)(g_Abuf + ((size_t)s << 8) + j0);
        float4 a0 = A4[0], a1 = A4[1];

        ag0.x += fmaxf(fmaf(d, w0.x, a0.x + b0.x + c0.x), 0.f);
        ag0.y += fmaxf(fmaf(d, w0.y, a0.y + b0.y + c0.y), 0.f);
        ag0.z += fmaxf(fmaf(d, w0.z, a0.z + b0.z + c0.z), 0.f);
        ag0.w += fmaxf(fmaf(d, w0.w, a0.w + b0.w + c0.w), 0.f);
        ag1.x += fmaxf(fmaf(d, w1.x, a1.x + b1.x + c1.x), 0.f);
        ag1.y += fmaxf(fmaf(d, w1.y, a1.y + b1.y + c1.y), 0.f);
        ag1.z += fmaxf(fmaf(d, w1.z, a1.z + b1.z + c1.z), 0.f);
        ag1.w += fmaxf(fmaf(d, w1.w, a1.w + b1.w + c1.w), 0.f);
    }

    float* ag = g_agg + ((size_t)node << 8) + j0;
    *(float4*)ag       = ag0;
    *(float4*)(ag + 4) = ag1;
}

// ---------------- launch ----------------------------------------------------
extern "C" void kernel_launch(void* const* d_in, const int* in_sizes, int n_in,
                              void* d_out, int out_size) {
    const float* x         = (const float*)d_in[0];
    const float* positions = (const float*)d_in[1];
    const float* W_in      = (const float*)d_in[2];
    const float* b_in      = (const float*)d_in[3];
    const float* Wg1       = (const float*)d_in[4];
    const float* bg1       = (const float*)d_in[5];
    const float* Wg2       = (const float*)d_in[6];
    const float* bg2       = (const float*)d_in[7];
    const float* Wm        = (const float*)d_in[8];
    const float* bm        = (const float*)d_in[9];
    const float* Wu        = (const float*)d_in[10];
    const float* bu        = (const float*)d_in[11];
    const float* Wp        = (const float*)d_in[12];
    const float* Wout      = (const float*)d_in[13];
    const float* bout      = (const float*)d_in[14];
    const int*   ei        = (const int*)d_in[15];
    float* out = (float*)d_out;

    static float* h1 = nullptr;
    static float* h2 = nullptr;
    static float* abuf = nullptr;
    static float* bbuf = nullptr;
    static float* aggp = nullptr;
    static __nv_bfloat16 *wmh, *wml, *wuh, *wul;
    if (!h1) {
        cudaGetSymbolAddress((void**)&h1,   g_h1buf);
        cudaGetSymbolAddress((void**)&h2,   g_h2buf);
        cudaGetSymbolAddress((void**)&abuf, g_Abuf);
        cudaGetSymbolAddress((void**)&bbuf, g_Bbuf);
        cudaGetSymbolAddress((void**)&aggp, g_agg);
        cudaGetSymbolAddress((void**)&wmh,  g_wm_h);
        cudaGetSymbolAddress((void**)&wml,  g_wm_l);
        cudaGetSymbolAddress((void**)&wuh,  g_wu_h);
        cudaGetSymbolAddress((void**)&wul,  g_wu_l);
        cudaFuncSetAttribute(k_mma, cudaFuncAttributeMaxDynamicSharedMemorySize, MM_SMEM);
    }

    // prologue (fused)
    k_wprep<<<320, 256>>>(Wm, Wu);
    k_meandgf<<<Nn, 256>>>(positions, Wg1, bg1, Wg2, bg2);
    k_hbinit<<<800, 256>>>(x, W_in, b_in, positions);
    k_small<<<390, 256>>>(Wm, Wu);
    k_hist<<<Ee / 256, 256>>>(ei);
    k_scan1<<<256, 256>>>();
    k_scan2<<<1, 256>>>();
    k_scan3<<<256, 256>>>();
    k_scatter<<<Ee / 256, 256>>>(ei);

    // ---- layer 0 (low-rank h0 path; pos2 = pos + delta fused in edge) ----
    k_edge2_lr<<<NNODE / 8, 256>>>(ei, Wm + 512 * 256, bm, Wp);
    k_mma<<<dim3(2, NNODE / 128), 256, MM_SMEM>>>(
        nullptr, aggp, wuh, wul, 512, 4, 8, 2,
        bu, nullptr, h1, nullptr, 0, nullptr, nullptr, nullptr, 0);

    // ---- layer 1 (full-rank; pos dead after, edge slimmed) ----
    const float* Wml = Wm + (size_t)513 * 256;
    k_mma<<<dim3(4, NNODE / 128), 256, MM_SMEM>>>(
        h1, nullptr, wmh + (size_t)2 * 65536, wml + (size_t)2 * 65536,
        256, 0, 4, 0, nullptr, nullptr, abuf, bbuf,
        2, nullptr, bout, out, 0);
    k_edge_l1<<<NNODE / 8, 256>>>(ei, Wml + 512 * 256, bm + 256);
    k_mma<<<dim3(2, NNODE / 128), 256, MM_SMEM>>>(
        h1, aggp, wuh + 131072, wul + 131072, 512, 0, 8, 1,
        bu + 256, h1, h2, nullptr, 0, Wout, bout, out, 1);
}

// round 17
// speedup vs baseline: 1.7463x; 1.1482x over previous
#include <cuda_runtime.h>
#include <cuda_bf16.h>
#include <cstdint>

#define Bb    32
#define Ff    128
#define Hh    256
#define Nn    2048
#define Ll    2
#define Ee    262144
#define NNODE 65536   // B*N

// ---------------- scratch (device globals; no allocation allowed) ----------
__device__ float g_h1buf[(size_t)NNODE * Hh];
__device__ float g_h2buf[(size_t)NNODE * Hh];
__device__ float g_Abuf [(size_t)NNODE * Hh];
__device__ float g_Bbuf [(size_t)NNODE * Hh];
__device__ float g_pos  [(size_t)NNODE * 3];
__device__ float g_pos2 [(size_t)NNODE * 3];
__device__ float g_hb   [Bb * Hh];
__device__ float g_gf   [Nn * Hh];
// pre-split bf16 activations
__device__ __nv_bfloat16 g_aggh[(size_t)NNODE * Hh];
__device__ __nv_bfloat16 g_aggl[(size_t)NNODE * Hh];
__device__ __nv_bfloat16 g_h1h [(size_t)NNODE * Hh];
__device__ __nv_bfloat16 g_h1l [(size_t)NNODE * Hh];
// low-rank layer-0 products: P[r][0:256]=h@Wm1, [256:512]=h@Wm2, [512:768]=h@Wu[0:256]
__device__ float g_P[(size_t)2080 * 768];
// edge sort-by-dst structures
__device__ int g_cnt [NNODE];
__device__ int g_cur [NNODE];
__device__ int g_off [NNODE + 1];
__device__ int g_bsum[256];
__device__ int g_perm[Ee];
// transposed, bf16 hi/lo split weights (layer-1 Wm at offset 2*65536; Wu both layers)
__device__ __nv_bfloat16 g_wm_h[(size_t)Ll * 2 * 256 * 256];
__device__ __nv_bfloat16 g_wm_l[(size_t)Ll * 2 * 256 * 256];
__device__ __nv_bfloat16 g_wu_h[(size_t)Ll * 256 * 512];
__device__ __nv_bfloat16 g_wu_l[(size_t)Ll * 256 * 512];

// ---------------- helpers ----------------------------------------------------
__device__ __forceinline__ uint32_t smem_u32(const void* p) {
    uint32_t a;
    asm("{ .reg .u64 t; cvta.to.shared.u64 t, %1; cvt.u32.u64 %0, t; }" : "=r"(a) : "l"(p));
    return a;
}
__device__ __forceinline__ uint32_t swz(uint32_t o) { return o ^ ((o >> 3) & 0x70); }

__device__ __forceinline__ void cpa16(uint32_t dst, const void* src) {
    asm volatile("cp.async.cg.shared.global [%0], [%1], 16;" :: "r"(dst), "l"(src));
}
#define CPCOMMIT() asm volatile("cp.async.commit_group;" ::: "memory")
#define CPWAIT0()  asm volatile("cp.async.wait_group 0;" ::: "memory")

#define LDSM4(r0, r1, r2, r3, a) \
    asm volatile("ldmatrix.sync.aligned.m8n8.x4.shared.b16 {%0,%1,%2,%3}, [%4];" \
        : "=r"(r0), "=r"(r1), "=r"(r2), "=r"(r3) : "r"(a))

#define MMA16816(d, a, b) \
    asm volatile("mma.sync.aligned.m16n8k16.row.col.f32.bf16.bf16.f32 " \
        "{%0,%1,%2,%3},{%4,%5,%6,%7},{%8,%9},{%0,%1,%2,%3};" \
        : "+f"((d)[0]), "+f"((d)[1]), "+f"((d)[2]), "+f"((d)[3]) \
        : "r"((a)[0]), "r"((a)[1]), "r"((a)[2]), "r"((a)[3]), "r"((b)[0]), "r"((b)[1]))

__device__ __forceinline__ void splitv(float v, __nv_bfloat16& h, __nv_bfloat16& l) {
    h = __float2bfloat16(v);
    l = __float2bfloat16(v - __bfloat162float(h));
}
__device__ __forceinline__ void split2(float a, float b, uint32_t& hi, uint32_t& lo) {
    __nv_bfloat16 ha, la, hb, lb;
    splitv(a, ha, la);
    splitv(b, hb, lb);
    hi = (uint32_t)__bfloat16_as_ushort(ha) | ((uint32_t)__bfloat16_as_ushort(hb) << 16);
    lo = (uint32_t)__bfloat16_as_ushort(la) | ((uint32_t)__bfloat16_as_ushort(lb) << 16);
}

// ---------------- weight prep: coalesced 32x32 tile transpose ---------------
__global__ __launch_bounds__(256) void k_wprep(const float* __restrict__ Wm,
                                               const float* __restrict__ Wu) {
    __shared__ float tile[32][33];
    int t = blockIdx.x;
    const float* src;
    __nv_bfloat16 *dh, *dl;
    int kbase, nbase, pitch;
    if (t < 128) {
        int mat = t >> 6, r = t & 63;
        int kt = r >> 3, nt = r & 7;
        src = Wm + (size_t)513 * 256 + (size_t)mat * 256 * 256;
        dh = g_wm_h + (size_t)(2 + mat) * 65536;
        dl = g_wm_l + (size_t)(2 + mat) * 65536;
        kbase = kt * 32; nbase = nt * 32; pitch = 256;
    } else if (t < 192) {
        int r = t - 128;
        int kt = r >> 3, nt = r & 7;
        src = Wu;
        dh = g_wu_h; dl = g_wu_l;
        kbase = 256 + kt * 32; nbase = nt * 32; pitch = 512;
    } else {
        int r = t - 192;
        int kt = r >> 3, nt = r & 7;
        src = Wu + (size_t)512 * 256;
        dh = g_wu_h + 131072; dl = g_wu_l + 131072;
        kbase = kt * 32; nbase = nt * 32; pitch = 512;
    }
    int tx = threadIdx.x & 31, ty = threadIdx.x >> 5;
    #pragma unroll
    for (int i = 0; i < 4; i++) {
        int k = kbase + ty + i * 8;
        tile[ty + i * 8][tx] = src[(size_t)k * 256 + nbase + tx];
    }
    __syncthreads();
    #pragma unroll
    for (int i = 0; i < 4; i++) {
        int n = nbase + ty + i * 8;
        float v = tile[tx][ty + i * 8];
        __nv_bfloat16 h, lo;
        splitv(v, h, lo);
        size_t o = (size_t)n * pitch + kbase + tx;
        dh[o] = h;
        dl[o] = lo;
    }
}

// ---------------- fused meand + gfeat ----------------------------------------
__global__ void k_meandgf(const float* __restrict__ positions,
                          const float* __restrict__ Wg1, const float* __restrict__ bg1,
                          const float* __restrict__ Wg2, const float* __restrict__ bg2) {
    __shared__ float sp[Nn * 3];
    __shared__ float red[256];
    __shared__ float t[Ff];
    int i = blockIdx.x;
    for (int k = threadIdx.x; k < Nn * 3; k += 256) sp[k] = positions[k];
    __syncthreads();
    float px = sp[i * 3], py = sp[i * 3 + 1], pz = sp[i * 3 + 2];
    float sum = 0.f;
    for (int j = threadIdx.x; j < Nn; j += 256) {
        if (j == i) continue;
        float dx = px - sp[j * 3], dy = py - sp[j * 3 + 1], dz = pz - sp[j * 3 + 2];
        sum += sqrtf(dx * dx + dy * dy + dz * dz);
    }
    red[threadIdx.x] = sum;
    __syncthreads();
    for (int s = 128; s; s >>= 1) {
        if (threadIdx.x < s) red[threadIdx.x] += red[threadIdx.x + s];
        __syncthreads();
    }
    float m = red[0] / (float)(Nn - 1);
    if (threadIdx.x < 128) {
        int kk = threadIdx.x;
        float w = Wg1[kk] + Wg1[128 + kk] + Wg1[256 + kk];
        t[kk] = fmaxf(fmaf(m, w, bg1[kk]), 0.f);
    }
    __syncthreads();
    int j = threadIdx.x;
    float acc = bg2[j];
    #pragma unroll 4
    for (int kk = 0; kk < 128; kk++) acc = fmaf(t[kk], Wg2[kk * Hh + j], acc);
    g_gf[i * Hh + j] = acc;
}

// ---------------- fused hbase + initpos + cnt-zero ---------------------------
__global__ void k_hbinit(const float* __restrict__ x, const float* __restrict__ W_in,
                         const float* __restrict__ b_in, const float* __restrict__ positions) {
    if (blockIdx.x < 32) {
        __shared__ float xb[Ff];
        int b = blockIdx.x;
        if (threadIdx.x < Ff) xb[threadIdx.x] = x[b * Ff + threadIdx.x];
        __syncthreads();
        int j = threadIdx.x;
        float acc = b_in[j];
        #pragma unroll 4
        for (int k = 0; k < Ff; k++) acc = fmaf(xb[k], W_in[k * Hh + j], acc);
        g_hb[b * Hh + j] = acc;
    } else {
        int i = (blockIdx.x - 32) * 256 + threadIdx.x;
        if (i < NNODE * 3) {
            int nd = i / 3;
            int k = i - nd * 3;
            g_pos[i] = positions[(nd & 2047) * 3 + k];
        }
        if (i < NNODE) g_cnt[i] = 0;
    }
}

// ---------------- edge counting sort (by dst) -------------------------------
__global__ void k_hist(const int* __restrict__ ei) {
    int e = blockIdx.x * 256 + threadIdx.x;
    atomicAdd(&g_cnt[ei[Ee + e]], 1);
}
__global__ void k_scan1() {
    __shared__ int sh[256];
    int t = threadIdx.x, b = blockIdx.x;
    int v = g_cnt[b * 256 + t];
    sh[t] = v;
    __syncthreads();
    for (int o = 1; o < 256; o <<= 1) {
        int u = (t >= o) ? sh[t - o] : 0;
        __syncthreads();
        sh[t] += u;
        __syncthreads();
    }
    g_off[b * 256 + t] = sh[t] - v;
    if (t == 255) g_bsum[b] = sh[255];
}
__global__ void k_scan2() {
    __shared__ int sh[256];
    int t = threadIdx.x;
    int v = g_bsum[t];
    sh[t] = v;
    __syncthreads();
    for (int o = 1; o < 256; o <<= 1) {
        int u = (t >= o) ? sh[t - o] : 0;
        __syncthreads();
        sh[t] += u;
        __syncthreads();
    }
    g_bsum[t] = sh[t] - v;
}
__global__ void k_scan3() {
    int i = blockIdx.x * 256 + threadIdx.x;
    int v = g_off[i] + g_bsum[blockIdx.x];
    g_off[i] = v;
    g_cur[i] = v;
    if (i == 0) g_off[NNODE] = Ee;
}
__global__ void k_scatter(const int* __restrict__ ei) {
    int e = blockIdx.x * 256 + threadIdx.x;
    int d = ei[Ee + e];
    int p = atomicAdd(&g_cur[d], 1);
    g_perm[p] = e;
}

// ---------------- low-rank layer-0 small GEMM (split by matrix, vec LDS) ----
__global__ __launch_bounds__(256) void k_small(const float* __restrict__ Wm,
                                               const float* __restrict__ Wu) {
    __shared__ float hs[16][260];
    int grp = blockIdx.x / 3;
    int mat = blockIdx.x - grp * 3;
    int r0 = grp * 16;
    int tid = threadIdx.x;
    for (int i = 0; i < 16; i++) {
        int r = r0 + i;
        const float* src = (r < 32) ? (g_hb + r * 256) : (g_gf + (size_t)(r - 32) * 256);
        hs[i][tid] = src[tid];
    }
    __syncthreads();

    const float* W = (mat == 0) ? Wm : (mat == 1) ? (Wm + 256 * 256) : Wu;
    float a[16];
    #pragma unroll
    for (int i = 0; i < 16; i++) a[i] = 0.f;

    for (int k0 = 0; k0 < 256; k0 += 8) {
        float wr[8];
        #pragma unroll
        for (int u = 0; u < 8; u++)
            wr[u] = __ldg(W + (size_t)(k0 + u) * 256 + tid);
        #pragma unroll
        for (int i = 0; i < 16; i++) {
            float4 h0 = *(const float4*)&hs[i][k0];
            float4 h1 = *(const float4*)&hs[i][k0 + 4];
            float ai = a[i];
            ai = fmaf(h0.x, wr[0], ai);
            ai = fmaf(h0.y, wr[1], ai);
            ai = fmaf(h0.z, wr[2], ai);
            ai = fmaf(h0.w, wr[3], ai);
            ai = fmaf(h1.x, wr[4], ai);
            ai = fmaf(h1.y, wr[5], ai);
            ai = fmaf(h1.z, wr[6], ai);
            ai = fmaf(h1.w, wr[7], ai);
            a[i] = ai;
        }
    }
    #pragma unroll
    for (int i = 0; i < 16; i++)
        g_P[(size_t)(r0 + i) * 768 + mat * 256 + tid] = a[i];
}

// ---------------- HMMA GEMM: all-cp.async staging, 2 CTAs/SM ----------------
// A operands are PRE-SPLIT bf16 (hi/lo), pitch 256: chunks c<4 read Ah0/Al0,
// c>=4 read Ah1/Al1. B is pre-split weights, pitch bpitch.
// mode 0: proj store (+out init); mode 1: residual+relu (+GEMV);
// mode 2: L0 update with low-rank h-part; also emits bf16 hi/lo of out (osh/osl).
#define MM_SMEM 65536

__global__ __launch_bounds__(256, 2) void k_mma(
    const __nv_bfloat16* __restrict__ Ah0, const __nv_bfloat16* __restrict__ Al0,
    const __nv_bfloat16* __restrict__ Ah1, const __nv_bfloat16* __restrict__ Al1,
    const __nv_bfloat16* __restrict__ Bh, const __nv_bfloat16* __restrict__ Bl,
    int bpitch, int cstart, int nchunks, int mode,
    const float* __restrict__ bias, const float* __restrict__ Xres,
    float* __restrict__ out0, float* __restrict__ out1,
    int zflags,
    const float* __restrict__ Wout, const float* __restrict__ bout,
    float* __restrict__ outv, int wantout,
    __nv_bfloat16* __restrict__ osh, __nv_bfloat16* __restrict__ osl)
{
    extern __shared__ char smem[];
    uint32_t sb = smem_u32(smem);
    int tid = threadIdx.x, wid = tid >> 5, lane = tid & 31;
    int row0 = blockIdx.y * 128, n0 = blockIdx.x * 128;
    int wm = wid & 3, wn = wid >> 2;

    float acc[2][8][4];
    #pragma unroll
    for (int a = 0; a < 2; a++)
        #pragma unroll
        for (int b = 0; b < 8; b++)
            #pragma unroll
            for (int c = 0; c < 4; c++) acc[a][b][c] = 0.f;

    auto stage_a = [&](int c) {
        const __nv_bfloat16* Ah = (c < 4) ? Ah0 : Ah1;
        const __nv_bfloat16* Al = (c < 4) ? Al0 : Al1;
        int cb = (c & 3) * 64;
        #pragma unroll
        for (int i = 0; i < 4; i++) {
            int g = i * 256 + tid;
            int row = g >> 3, c8 = g & 7;
            uint32_t off = swz(row * 128 + c8 * 16);
            const __nv_bfloat16* sh = Ah + (size_t)(row0 + row) * 256 + cb + c8 * 8;
            const __nv_bfloat16* sl = Al + (size_t)(row0 + row) * 256 + cb + c8 * 8;
            cpa16(sb + off, sh);
            cpa16(sb + 16384 + off, sl);
        }
    };
    auto stage_b = [&](int c) {
        uint32_t base = sb + 32768;
        #pragma unroll
        for (int i = 0; i < 8; i++) {
            int g = i * 256 + tid;
            int sp = g >> 10, r = g & 1023;
            int row = r >> 3, c8 = r & 7;
            const __nv_bfloat16* src = (sp ? Bl : Bh)
                + (size_t)(n0 + row) * bpitch + c * 64 + c8 * 8;
            cpa16(base + sp * 16384 + swz(row * 128 + c8 * 16), src);
        }
    };

    for (int c = cstart; c < nchunks; c++) {
        __syncthreads();
        stage_a(c);
        stage_b(c);
        CPCOMMIT();
        CPWAIT0();
        __syncthreads();

        int arow = wm * 32 + (lane & 7) + ((lane >> 3) & 1) * 8;
        int akb = ((lane >> 4) & 1) * 16;
        int brow = wn * 64 + (lane & 7) + ((lane >> 4) & 1) * 8;
        int bkb = ((lane >> 3) & 1) * 16;

        #pragma unroll
        for (int k16 = 0; k16 < 4; k16++) {
            uint32_t a_h[2][4], a_l[2][4], b_h[8][2], b_l[8][2];
            #pragma unroll
            for (int mf = 0; mf < 2; mf++) {
                uint32_t ad = sb + swz((arow + mf * 16) * 128 + k16 * 32 + akb);
                LDSM4(a_h[mf][0], a_h[mf][1], a_h[mf][2], a_h[mf][3], ad);
                LDSM4(a_l[mf][0], a_l[mf][1], a_l[mf][2], a_l[mf][3], ad + 16384);
            }
            #pragma unroll
            for (int nf2 = 0; nf2 < 4; nf2++) {
                uint32_t bd = sb + 32768 + swz((brow + nf2 * 16) * 128 + k16 * 32 + bkb);
                LDSM4(b_h[2 * nf2][0], b_h[2 * nf2][1],
                      b_h[2 * nf2 + 1][0], b_h[2 * nf2 + 1][1], bd);
                LDSM4(b_l[2 * nf2][0], b_l[2 * nf2][1],
                      b_l[2 * nf2 + 1][0], b_l[2 * nf2 + 1][1], bd + 16384);
            }
            #pragma unroll
            for (int mf = 0; mf < 2; mf++)
                #pragma unroll
                for (int nf = 0; nf < 8; nf++) {
                    MMA16816(acc[mf][nf], a_h[mf], b_h[nf]);
                    MMA16816(acc[mf][nf], a_h[mf], b_l[nf]);
                    MMA16816(acc[mf][nf], a_l[mf], b_h[nf]);
                }
        }
    }

    // ---------------- epilogue ----------------
    int r_base = row0 + wm * 32 + (lane >> 2);
    int c_base = n0 + wn * 64 + 2 * (lane & 3);
    if (mode == 0) {
        #pragma unroll
        for (int mf = 0; mf < 2; mf++)
            #pragma unroll
            for (int nf = 0; nf < 8; nf++) {
                int r = r_base + mf * 16;
                int col = c_base + nf * 8;
                float* ob = (col < 256) ? out0 : out1;
                int cc = col & 255;
                *(float2*)(ob + (size_t)r * 256 + cc) =
                    make_float2(acc[mf][nf][0], acc[mf][nf][1]);
                *(float2*)(ob + (size_t)(r + 8) * 256 + cc) =
                    make_float2(acc[mf][nf][2], acc[mf][nf][3]);
            }
        if (blockIdx.x == 0 && (zflags & 2) && tid < 128) outv[row0 + tid] = bout[0];
    } else if (mode == 1) {
        float wpart[2][2] = {{0.f, 0.f}, {0.f, 0.f}};
        #pragma unroll
        for (int mf = 0; mf < 2; mf++)
            #pragma unroll
            for (int nf = 0; nf < 8; nf++) {
                int col = c_base + nf * 8;
                float b0 = bias[col], b1 = bias[col + 1];
                float w0 = 0.f, w1 = 0.f;
                if (wantout) { w0 = Wout[col]; w1 = Wout[col + 1]; }
                #pragma unroll
                for (int hr = 0; hr < 2; hr++) {
                    int r = r_base + mf * 16 + hr * 8;
                    size_t off = (size_t)r * 256 + col;
                    float2 xv = *(const float2*)(Xres + off);
                    float o0 = xv.x + fmaxf(acc[mf][nf][hr * 2]     + b0, 0.f);
                    float o1 = xv.y + fmaxf(acc[mf][nf][hr * 2 + 1] + b1, 0.f);
                    *(float2*)(out0 + off) = make_float2(o0, o1);
                    wpart[mf][hr] += o0 * w0 + o1 * w1;
                }
            }
        if (wantout) {
            #pragma unroll
            for (int mf = 0; mf < 2; mf++)
                #pragma unroll
                for (int hr = 0; hr < 2; hr++) {
                    float v = wpart[mf][hr];
                    v += __shfl_xor_sync(0xffffffffu, v, 1);
                    v += __shfl_xor_sync(0xffffffffu, v, 2);
                    if ((lane & 3) == 0)
                        atomicAdd(outv + r_base + mf * 16 + hr * 8, v);
                }
        }
    } else {
        // mode 2: layer-0 update; emit fp32 out AND bf16 hi/lo splits
        #pragma unroll
        for (int mf = 0; mf < 2; mf++)
            #pragma unroll
            for (int nf = 0; nf < 8; nf++) {
                int col = c_base + nf * 8;
                float b0 = bias[col], b1 = bias[col + 1];
                #pragma unroll
                for (int hr = 0; hr < 2; hr++) {
                    int r = r_base + mf * 16 + hr * 8;
                    int bb = r >> 11, nn = r & 2047;
                    const float* hbr = g_hb + bb * 256 + col;
                    const float* gfr = g_gf + (size_t)nn * 256 + col;
                    const float* phr = g_P + (size_t)bb * 768 + 512 + col;
                    const float* pgr = g_P + (size_t)(32 + nn) * 768 + 512 + col;
                    float x0 = hbr[0] + gfr[0];
                    float x1 = hbr[1] + gfr[1];
                    float ci0 = phr[0] + pgr[0];
                    float ci1 = phr[1] + pgr[1];
                    float o0 = x0 + fmaxf(acc[mf][nf][hr * 2]     + ci0 + b0, 0.f);
                    float o1 = x1 + fmaxf(acc[mf][nf][hr * 2 + 1] + ci1 + b1, 0.f);
                    size_t off = (size_t)r * 256 + col;
                    *(float2*)(out0 + off) = make_float2(o0, o1);
                    uint32_t ph, pl;
                    split2(o0, o1, ph, pl);
                    *(uint32_t*)(osh + off) = ph;
                    *(uint32_t*)(osl + off) = pl;
                }
            }
    }
}

// ---------------- edge kernels: 1 warp / dst node ---------------------------
// Layer 0, low-rank: A/B from g_P; writes agg as bf16 hi/lo + pos2.
__global__ __launch_bounds__(256) void k_edge2_lr(const int* __restrict__ ei,
                                                  const float* __restrict__ wd,
                                                  const float* __restrict__ bmv,
                                                  const float* __restrict__ wp) {
    int node = (blockIdx.x << 3) + (threadIdx.x >> 5);
    int lane = threadIdx.x & 31;
    int beg = g_off[node], end = g_off[node + 1];
    int j0 = lane << 3;

    float4 w0 = *(const float4*)(wd + j0),  w1 = *(const float4*)(wd + j0 + 4);
    float4 c0 = *(const float4*)(bmv + j0), c1 = *(const float4*)(bmv + j0 + 4);
    float4 p0 = *(const float4*)(wp + j0),  p1 = *(const float4*)(wp + j0 + 4);

    int bt = node >> 11, nt = node & 2047;
    const float4* pb = (const float4*)(g_P + (size_t)bt * 768 + 256 + j0);
    const float4* pg = (const float4*)(g_P + (size_t)(32 + nt) * 768 + 256 + j0);
    float4 q0 = pb[0], q1 = pb[1], r0 = pg[0], r1 = pg[1];
    float4 b0 = make_float4(q0.x + r0.x, q0.y + r0.y, q0.z + r0.z, q0.w + r0.w);
    float4 b1 = make_float4(q1.x + r1.x, q1.y + r1.y, q1.z + r1.z, q1.w + r1.w);

    float ptx = g_pos[node * 3], pty = g_pos[node * 3 + 1], ptz = g_pos[node * 3 + 2];

    float4 ag0 = make_float4(0.f, 0.f, 0.f, 0.f);
    float4 ag1 = make_float4(0.f, 0.f, 0.f, 0.f);
    float pa = 0.f;

    for (int i = beg; i < end; i++) {
        int e = g_perm[i];
        int s = __ldg(ei + e);
        float psx = g_pos[s * 3], psy = g_pos[s * 3 + 1], psz = g_pos[s * 3 + 2];
        float dx = psx - ptx, dy = psy - pty, dz = psz - ptz;
        float d = sqrtf(dx * dx + dy * dy + dz * dz + 1e-12f);

        int bs = s >> 11, ns = s & 2047;
        const float4* ab = (const float4*)(g_P + (size_t)bs * 768 + j0);
        const float4* ag4 = (const float4*)(g_P + (size_t)(32 + ns) * 768 + j0);
        float4 u0 = ab[0], u1 = ab[1], v0 = ag4[0], v1 = ag4[1];
        float4 a0 = make_float4(u0.x + v0.x, u0.y + v0.y, u0.z + v0.z, u0.w + v0.w);
        float4 a1 = make_float4(u1.x + v1.x, u1.y + v1.y, u1.z + v1.z, u1.w + v1.w);

        float4 m0, m1;
        m0.x = fmaxf(fmaf(d, w0.x, a0.x + b0.x + c0.x), 0.f);
        m0.y = fmaxf(fmaf(d, w0.y, a0.y + b0.y + c0.y), 0.f);
        m0.z = fmaxf(fmaf(d, w0.z, a0.z + b0.z + c0.z), 0.f);
        m0.w = fmaxf(fmaf(d, w0.w, a0.w + b0.w + c0.w), 0.f);
        m1.x = fmaxf(fmaf(d, w1.x, a1.x + b1.x + c1.x), 0.f);
        m1.y = fmaxf(fmaf(d, w1.y, a1.y + b1.y + c1.y), 0.f);
        m1.z = fmaxf(fmaf(d, w1.z, a1.z + b1.z + c1.z), 0.f);
        m1.w = fmaxf(fmaf(d, w1.w, a1.w + b1.w + c1.w), 0.f);

        ag0.x += m0.x; ag0.y += m0.y; ag0.z += m0.z; ag0.w += m0.w;
        ag1.x += m1.x; ag1.y += m1.y; ag1.z += m1.z; ag1.w += m1.w;

        float cf = m0.x * p0.x + m0.y * p0.y + m0.z * p0.z + m0.w * p0.w
                 + m1.x * p1.x + m1.y * p1.y + m1.z * p1.z + m1.w * p1.w;
        #pragma unroll
        for (int off = 16; off; off >>= 1) cf += __shfl_xor_sync(0xffffffffu, cf, off);

        if (lane < 3) {
            float pd = (lane == 0) ? (ptx - psx) : (lane == 1) ? (pty - psy) : (ptz - psz);
            pa += pd * cf;
        }
    }

    size_t aoff = ((size_t)node << 8) + j0;
    uint4 hi, lo;
    split2(ag0.x, ag0.y, hi.x, lo.x);
    split2(ag0.z, ag0.w, hi.y, lo.y);
    split2(ag1.x, ag1.y, hi.z, lo.z);
    split2(ag1.z, ag1.w, hi.w, lo.w);
    *(uint4*)(g_aggh + aoff) = hi;
    *(uint4*)(g_aggl + aoff) = lo;
    if (lane < 3) {
        float pt = (lane == 0) ? ptx : (lane == 1) ? pty : ptz;
        g_pos2[node * 3 + lane] = pt + pa * 0.25f;
    }
}

// Layer 1, full-rank: reads Abuf/Bbuf (fp32) and pos2; writes agg bf16 hi/lo.
__global__ __launch_bounds__(256) void k_edge_l1(const int* __restrict__ ei,
                                                 const float* __restrict__ wd,
                                                 const float* __restrict__ bmv) {
    int node = (blockIdx.x << 3) + (threadIdx.x >> 5);
    int lane = threadIdx.x & 31;
    int beg = g_off[node], end = g_off[node + 1];
    int j0 = lane << 3;

    float4 w0 = *(const float4*)(wd + j0),  w1 = *(const float4*)(wd + j0 + 4);
    float4 c0 = *(const float4*)(bmv + j0), c1 = *(const float4*)(bmv + j0 + 4);
    const float4* B4 = (const float4*)(g_Bbuf + ((size_t)node << 8) + j0);
    float4 b0 = B4[0], b1 = B4[1];
    float ptx = g_pos2[node * 3], pty = g_pos2[node * 3 + 1], ptz = g_pos2[node * 3 + 2];

    float4 ag0 = make_float4(0.f, 0.f, 0.f, 0.f);
    float4 ag1 = make_float4(0.f, 0.f, 0.f, 0.f);

    for (int i = beg; i < end; i++) {
        int e = g_perm[i];
        int s = __ldg(ei + e);
        float psx = g_pos2[s * 3], psy = g_pos2[s * 3 + 1], psz = g_pos2[s * 3 + 2];
        float dx = psx - ptx, dy = psy - pty, dz = psz - ptz;
        float d = sqrtf(dx * dx + dy * dy + dz * dz + 1e-12f);

        const float4* A4 = (const float4*)(g_Abuf + ((size_t)s << 8) + j0);
        float4 a0 = A4[0], a1 = A4[1];

        ag0.x += fmaxf(fmaf(d, w0.x, a0.x + b0.x + c0.x), 0.f);
        ag0.y += fmaxf(fmaf(d, w0.y, a0.y + b0.y + c0.y), 0.f);
        ag0.z += fmaxf(fmaf(d, w0.z, a0.z + b0.z + c0.z), 0.f);
        ag0.w += fmaxf(fmaf(d, w0.w, a0.w + b0.w + c0.w), 0.f);
        ag1.x += fmaxf(fmaf(d, w1.x, a1.x + b1.x + c1.x), 0.f);
        ag1.y += fmaxf(fmaf(d, w1.y, a1.y + b1.y + c1.y), 0.f);
        ag1.z += fmaxf(fmaf(d, w1.z, a1.z + b1.z + c1.z), 0.f);
        ag1.w += fmaxf(fmaf(d, w1.w, a1.w + b1.w + c1.w), 0.f);
    }

    size_t aoff = ((size_t)node << 8) + j0;
    uint4 hi, lo;
    split2(ag0.x, ag0.y, hi.x, lo.x);
    split2(ag0.z, ag0.w, hi.y, lo.y);
    split2(ag1.x, ag1.y, hi.z, lo.z);
    split2(ag1.z, ag1.w, hi.w, lo.w);
    *(uint4*)(g_aggh + aoff) = hi;
    *(uint4*)(g_aggl + aoff) = lo;
}

// ---------------- launch ----------------------------------------------------
extern "C" void kernel_launch(void* const* d_in, const int* in_sizes, int n_in,
                              void* d_out, int out_size) {
    const float* x         = (const float*)d_in[0];
    const float* positions = (const float*)d_in[1];
    const float* W_in      = (const float*)d_in[2];
    const float* b_in      = (const float*)d_in[3];
    const float* Wg1       = (const float*)d_in[4];
    const float* bg1       = (const float*)d_in[5];
    const float* Wg2       = (const float*)d_in[6];
    const float* bg2       = (const float*)d_in[7];
    const float* Wm        = (const float*)d_in[8];
    const float* bm        = (const float*)d_in[9];
    const float* Wu        = (const float*)d_in[10];
    const float* bu        = (const float*)d_in[11];
    const float* Wp        = (const float*)d_in[12];
    const float* Wout      = (const float*)d_in[13];
    const float* bout      = (const float*)d_in[14];
    const int*   ei        = (const int*)d_in[15];
    float* out = (float*)d_out;

    static float* h1 = nullptr;
    static float* h2 = nullptr;
    static float* abuf = nullptr;
    static float* bbuf = nullptr;
    static __nv_bfloat16 *aggh, *aggl, *h1h, *h1l, *wmh, *wml, *wuh, *wul;
    if (!h1) {
        cudaGetSymbolAddress((void**)&h1,   g_h1buf);
        cudaGetSymbolAddress((void**)&h2,   g_h2buf);
        cudaGetSymbolAddress((void**)&abuf, g_Abuf);
        cudaGetSymbolAddress((void**)&bbuf, g_Bbuf);
        cudaGetSymbolAddress((void**)&aggh, g_aggh);
        cudaGetSymbolAddress((void**)&aggl, g_aggl);
        cudaGetSymbolAddress((void**)&h1h,  g_h1h);
        cudaGetSymbolAddress((void**)&h1l,  g_h1l);
        cudaGetSymbolAddress((void**)&wmh,  g_wm_h);
        cudaGetSymbolAddress((void**)&wml,  g_wm_l);
        cudaGetSymbolAddress((void**)&wuh,  g_wu_h);
        cudaGetSymbolAddress((void**)&wul,  g_wu_l);
        cudaFuncSetAttribute(k_mma, cudaFuncAttributeMaxDynamicSharedMemorySize, MM_SMEM);
    }

    // prologue (fused)
    k_wprep<<<320, 256>>>(Wm, Wu);
    k_meandgf<<<Nn, 256>>>(positions, Wg1, bg1, Wg2, bg2);
    k_hbinit<<<800, 256>>>(x, W_in, b_in, positions);
    k_small<<<390, 256>>>(Wm, Wu);
    k_hist<<<Ee / 256, 256>>>(ei);
    k_scan1<<<256, 256>>>();
    k_scan2<<<1, 256>>>();
    k_scan3<<<256, 256>>>();
    k_scatter<<<Ee / 256, 256>>>(ei);

    // ---- layer 0 (low-rank h0 path) ----
    k_edge2_lr<<<NNODE / 8, 256>>>(ei, Wm + 512 * 256, bm, Wp);
    // update-L0: h1 = (hb+gf) + relu(agg@Wu[256:512] + Pu + bu); emits h1 bf16 splits
    k_mma<<<dim3(2, NNODE / 128), 256, MM_SMEM>>>(
        nullptr, nullptr, aggh, aggl, wuh, wul, 512, 4, 8, 2,
        bu, nullptr, h1, nullptr, 0, nullptr, nullptr, nullptr, 0, h1h, h1l);

    // ---- layer 1 (full-rank) ----
    const float* Wml = Wm + (size_t)513 * 256;
    k_mma<<<dim3(4, NNODE / 128), 256, MM_SMEM>>>(
        h1h, h1l, nullptr, nullptr,
        wmh + (size_t)2 * 65536, wml + (size_t)2 * 65536,
        256, 0, 4, 0, nullptr, nullptr, abuf, bbuf,
        2, nullptr, bout, out, 0, nullptr, nullptr);
    k_edge_l1<<<NNODE / 8, 256>>>(ei, Wml + 512 * 256, bm + 256);
    k_mma<<<dim3(2, NNODE / 128), 256, MM_SMEM>>>(
        h1h, h1l, aggh, aggl, wuh + 131072, wul + 131072, 512, 0, 8, 1,
        bu + 256, h1, h2, nullptr, 0, Wout, bout, out, 1, nullptr, nullptr);
}